// round 1
// baseline (speedup 1.0000x reference)
#include <cuda_runtime.h>

#define NN 40000
#define NE 640000
#define ND 128
#define ED 64

// Scratch (static device allocations — allowed)
__device__ float g_AB[NN * 256];      // per-node A|B = nf@W1a | nf@W1b  (41 MB)
__device__ float g_agg[NN * ND];      // scatter-add target (20.5 MB)
__device__ float g_WtI[ND * 384];     // W_ih transposed [k][m]
__device__ float g_WtH[ND * 384];     // W_hh transposed [k][m]

__global__ void k_zero() {
    int i = blockIdx.x * blockDim.x + threadIdx.x;
    if (i < NN * ND / 4)
        reinterpret_cast<float4*>(g_agg)[i] = make_float4(0.f, 0.f, 0.f, 0.f);
}

__global__ void k_transpose(const float* __restrict__ Wih, const float* __restrict__ Whh) {
    int idx = blockIdx.x * blockDim.x + threadIdx.x;
    if (idx < 384 * ND) {
        int k = idx / 384, m = idx % 384;
        g_WtI[idx] = Wih[m * ND + k];
        g_WtH[idx] = Whh[m * ND + k];
    }
}

// A[n][j] = sum_k nf[n][k] * W1[k][j]; B[n][j] = sum_k nf[n][k] * W1[128+k][j]
__global__ void __launch_bounds__(128) k_nodeAB(const float* __restrict__ nf,
                                                const float* __restrict__ W1) {
    __shared__ float sx[8][ND];
    int j = threadIdx.x;
    int base = blockIdx.x * 8;
    #pragma unroll
    for (int n = 0; n < 8; n++) sx[n][j] = nf[(base + n) * ND + j];
    __syncthreads();
    float accA[8], accB[8];
    #pragma unroll
    for (int n = 0; n < 8; n++) { accA[n] = 0.f; accB[n] = 0.f; }
    for (int k = 0; k < ND; k++) {
        float wa = W1[k * ND + j];
        float wb = W1[(ND + k) * ND + j];
        #pragma unroll
        for (int n = 0; n < 8; n++) {
            float x = sx[n][k];
            accA[n] = fmaf(x, wa, accA[n]);
            accB[n] = fmaf(x, wb, accB[n]);
        }
    }
    #pragma unroll
    for (int n = 0; n < 8; n++) {
        g_AB[(base + n) * 256 + j]      = accA[n];
        g_AB[(base + n) * 256 + ND + j] = accB[n];
    }
}

// Edge kernel: 4 edges per block-iteration, thread j owns output column j.
__global__ void __launch_bounds__(128) k_edge(
    const float* __restrict__ ef, const int* __restrict__ ei,
    const float* __restrict__ W1, const float* __restrict__ b1,
    const float* __restrict__ lng, const float* __restrict__ lnb,
    const float* __restrict__ W2, const float* __restrict__ b2,
    const float* __restrict__ gw, const float* __restrict__ gb) {
    __shared__ float sef[4][ED];
    __shared__ float sh[4][ND];
    __shared__ float sred[2][4][4];   // [sum|sumsq][warp][edge]
    int j = threadIdx.x;
    int lane = j & 31, w = j >> 5;
    float bj1 = b1[j], bj2 = b2[j], gscale = lng[j], gbias = lnb[j], gb0 = gb[0];

    for (int e0 = blockIdx.x * 4; e0 < NE; e0 += gridDim.x * 4) {
        int src[4], dst[4];
        #pragma unroll
        for (int t = 0; t < 4; t++) { src[t] = ei[e0 + t]; dst[t] = ei[NE + e0 + t]; }
        {   // stage 4x64 edge features: each thread writes 2
            int t = j >> 6, c = j & 63;
            sef[t][c]     = ef[(e0 + t) * ED + c];
            sef[t + 2][c] = ef[(e0 + t + 2) * ED + c];
        }
        __syncthreads();

        // h = b1 + ef@W1c  (and gate accumulator), amortize weight loads over 4 edges
        float h[4], gacc[4];
        #pragma unroll
        for (int t = 0; t < 4; t++) { h[t] = bj1; gacc[t] = gb0; }
        for (int k = 0; k < ED; k++) {
            float wc = W1[(256 + k) * ND + j];
            float gwk = gw[k];
            #pragma unroll
            for (int t = 0; t < 4; t++) {
                float x = sef[t][k];
                h[t]    = fmaf(x, wc, h[t]);
                gacc[t] = fmaf(x, gwk, gacc[t]);
            }
        }
        // + A[src] + B[dst]  (L2-resident table)
        #pragma unroll
        for (int t = 0; t < 4; t++)
            h[t] += g_AB[src[t] * 256 + j] + g_AB[dst[t] * 256 + ND + j];

        // LayerNorm over 128 cols: warp shuffle + cross-warp smem reduce (4 edges at once)
        float s[4], s2[4];
        #pragma unroll
        for (int t = 0; t < 4; t++) { s[t] = h[t]; s2[t] = h[t] * h[t]; }
        #pragma unroll
        for (int o = 16; o; o >>= 1) {
            #pragma unroll
            for (int t = 0; t < 4; t++) {
                s[t]  += __shfl_xor_sync(0xffffffffu, s[t], o);
                s2[t] += __shfl_xor_sync(0xffffffffu, s2[t], o);
            }
        }
        if (lane == 0) {
            #pragma unroll
            for (int t = 0; t < 4; t++) { sred[0][w][t] = s[t]; sred[1][w][t] = s2[t]; }
        }
        __syncthreads();
        #pragma unroll
        for (int t = 0; t < 4; t++) {
            float ss  = sred[0][0][t] + sred[0][1][t] + sred[0][2][t] + sred[0][3][t];
            float ss2 = sred[1][0][t] + sred[1][1][t] + sred[1][2][t] + sred[1][3][t];
            float mu  = ss * (1.f / ND);
            float var = ss2 * (1.f / ND) - mu * mu;
            float hn  = (h[t] - mu) * rsqrtf(var + 1e-5f) * gscale + gbias;
            sh[t][j] = fmaxf(hn, 0.f);
        }
        __syncthreads();

        // messages = relu(ln(h)) @ W2 + b2, gated, scatter-add
        float m[4];
        #pragma unroll
        for (int t = 0; t < 4; t++) m[t] = bj2;
        for (int k = 0; k < ND; k++) {
            float w2 = W2[k * ND + j];
            #pragma unroll
            for (int t = 0; t < 4; t++) m[t] = fmaf(sh[t][k], w2, m[t]);
        }
        #pragma unroll
        for (int t = 0; t < 4; t++) {
            float gate = 1.f / (1.f + __expf(-gacc[t]));
            atomicAdd(&g_agg[dst[t] * ND + j], m[t] * gate);
        }
        __syncthreads();
    }
}

// GRU: gi = agg@W_ih^T + b_ih; gh = nf@W_hh^T + b_hh; gates r,z,n
__global__ void __launch_bounds__(128) k_gru(const float* __restrict__ nf,
                                             const float* __restrict__ bih,
                                             const float* __restrict__ bhh,
                                             float* __restrict__ out) {
    __shared__ float sa[4][ND], sn[4][ND];
    int j = threadIdx.x;
    int base = blockIdx.x * 4;
    #pragma unroll
    for (int n = 0; n < 4; n++) {
        sa[n][j] = g_agg[(base + n) * ND + j];
        sn[n][j] = nf[(base + n) * ND + j];
    }
    __syncthreads();
    float gi[4][3], gh[4][3];
    #pragma unroll
    for (int n = 0; n < 4; n++)
        #pragma unroll
        for (int g = 0; g < 3; g++) { gi[n][g] = bih[g * ND + j]; gh[n][g] = bhh[g * ND + j]; }
    for (int k = 0; k < ND; k++) {
        float wi0 = g_WtI[k * 384 + j], wi1 = g_WtI[k * 384 + ND + j], wi2 = g_WtI[k * 384 + 2 * ND + j];
        float wh0 = g_WtH[k * 384 + j], wh1 = g_WtH[k * 384 + ND + j], wh2 = g_WtH[k * 384 + 2 * ND + j];
        #pragma unroll
        for (int n = 0; n < 4; n++) {
            float a = sa[n][k], x = sn[n][k];
            gi[n][0] = fmaf(a, wi0, gi[n][0]);
            gi[n][1] = fmaf(a, wi1, gi[n][1]);
            gi[n][2] = fmaf(a, wi2, gi[n][2]);
            gh[n][0] = fmaf(x, wh0, gh[n][0]);
            gh[n][1] = fmaf(x, wh1, gh[n][1]);
            gh[n][2] = fmaf(x, wh2, gh[n][2]);
        }
    }
    #pragma unroll
    for (int n = 0; n < 4; n++) {
        float r  = 1.f / (1.f + __expf(-(gi[n][0] + gh[n][0])));
        float z  = 1.f / (1.f + __expf(-(gi[n][1] + gh[n][1])));
        float nn = tanhf(gi[n][2] + r * gh[n][2]);
        out[(base + n) * ND + j] = (1.f - z) * nn + z * sn[n][j];
    }
}

extern "C" void kernel_launch(void* const* d_in, const int* in_sizes, int n_in,
                              void* d_out, int out_size) {
    const float* nf  = (const float*)d_in[0];
    const int*   ei  = (const int*)d_in[1];
    const float* ef  = (const float*)d_in[2];
    const float* W1  = (const float*)d_in[3];
    const float* b1  = (const float*)d_in[4];
    const float* lng = (const float*)d_in[5];
    const float* lnb = (const float*)d_in[6];
    const float* W2  = (const float*)d_in[7];
    const float* b2  = (const float*)d_in[8];
    const float* gw  = (const float*)d_in[9];
    const float* gb  = (const float*)d_in[10];
    const float* Wih = (const float*)d_in[11];
    const float* bih = (const float*)d_in[12];
    const float* Whh = (const float*)d_in[13];
    const float* bhh = (const float*)d_in[14];
    float* out = (float*)d_out;

    k_zero<<<(NN * ND / 4 + 255) / 256, 256>>>();
    k_transpose<<<(384 * ND + 255) / 256, 256>>>(Wih, Whh);
    k_nodeAB<<<NN / 8, 128>>>(nf, W1);
    k_edge<<<2368, 128>>>(ef, ei, W1, b1, lng, lnb, W2, b2, gw, gb);
    k_gru<<<NN / 4, 128>>>(nf, bih, bhh, out);
}

// round 2
// speedup vs baseline: 1.2771x; 1.2771x over previous
#include <cuda_runtime.h>

#define NN 40000
#define NE 640000
#define ND 128
#define ED 64

typedef unsigned long long u64;

// Scratch (static device allocations — allowed)
__device__ float g_AB[NN * 256];      // per-node A|B = nf@W1a | nf@W1b
__device__ float g_agg[NN * ND];      // scatter-add target
__device__ float g_WtI[ND * 384];     // W_ih transposed [k][m]
__device__ float g_WtH[ND * 384];     // W_hh transposed [k][m]

// ---- packed f32x2 helpers (sm_103a dual-fp32 pipe) ----
__device__ __forceinline__ u64 pk(float a, float b) {
    u64 d; asm("mov.b64 %0, {%1,%2};" : "=l"(d)
               : "r"(__float_as_uint(a)), "r"(__float_as_uint(b)));
    return d;
}
__device__ __forceinline__ float2 upk(u64 v) {
    unsigned a, b; asm("mov.b64 {%0,%1}, %2;" : "=r"(a), "=r"(b) : "l"(v));
    return make_float2(__uint_as_float(a), __uint_as_float(b));
}
__device__ __forceinline__ u64 fma2(u64 a, u64 b, u64 c) {
    u64 d; asm("fma.rn.f32x2 %0, %1, %2, %3;" : "=l"(d) : "l"(a), "l"(b), "l"(c));
    return d;
}
__device__ __forceinline__ u64 add2(u64 a, u64 b) {
    u64 d; asm("add.rn.f32x2 %0, %1, %2;" : "=l"(d) : "l"(a), "l"(b));
    return d;
}
__device__ __forceinline__ u64 mul2(u64 a, u64 b) {
    u64 d; asm("mul.rn.f32x2 %0, %1, %2;" : "=l"(d) : "l"(a), "l"(b));
    return d;
}
__device__ __forceinline__ float fsig(float x) { return 1.f / (1.f + __expf(-x)); }
__device__ __forceinline__ float ftanh(float x) {
    float e = __expf(2.f * fabsf(x));
    return copysignf(1.f - 2.f / (e + 1.f), x);
}

__global__ void k_zero() {
    int i = blockIdx.x * blockDim.x + threadIdx.x;
    if (i < NN * ND / 4)
        reinterpret_cast<float4*>(g_agg)[i] = make_float4(0.f, 0.f, 0.f, 0.f);
}

__global__ void k_transpose(const float* __restrict__ Wih, const float* __restrict__ Whh) {
    int idx = blockIdx.x * blockDim.x + threadIdx.x;
    if (idx < 384 * ND) {
        int k = idx / 384, m = idx % 384;
        g_WtI[idx] = Wih[m * ND + k];
        g_WtH[idx] = Whh[m * ND + k];
    }
}

// A|B = nf @ [W1a | W1b], 8 nodes (4 packed pairs) per block
__global__ void __launch_bounds__(128) k_nodeAB(const float* __restrict__ nf,
                                                const float* __restrict__ W1) {
    __shared__ __align__(16) float sxp[4][ND * 2];
    int j = threadIdx.x;
    int base = blockIdx.x * 8;
    #pragma unroll
    for (int n = 0; n < 8; n++)
        sxp[n >> 1][j * 2 + (n & 1)] = nf[(base + n) * ND + j];
    __syncthreads();
    u64 accA[4] = {0, 0, 0, 0}, accB[4] = {0, 0, 0, 0};
    #pragma unroll 2
    for (int k = 0; k < ND; k += 2) {
        float wa0 = W1[k * ND + j], wa1 = W1[(k + 1) * ND + j];
        float wb0 = W1[(ND + k) * ND + j], wb1 = W1[(ND + k + 1) * ND + j];
        u64 wa0p = pk(wa0, wa0), wa1p = pk(wa1, wa1);
        u64 wb0p = pk(wb0, wb0), wb1p = pk(wb1, wb1);
        #pragma unroll
        for (int p = 0; p < 4; p++) {
            ulonglong2 xx = *(const ulonglong2*)&(((const u64*)sxp[p])[k]);
            accA[p] = fma2(xx.x, wa0p, accA[p]);
            accA[p] = fma2(xx.y, wa1p, accA[p]);
            accB[p] = fma2(xx.x, wb0p, accB[p]);
            accB[p] = fma2(xx.y, wb1p, accB[p]);
        }
    }
    #pragma unroll
    for (int p = 0; p < 4; p++) {
        float2 a = upk(accA[p]), b = upk(accB[p]);
        g_AB[(base + 2 * p) * 256 + j]          = a.x;
        g_AB[(base + 2 * p + 1) * 256 + j]      = a.y;
        g_AB[(base + 2 * p) * 256 + ND + j]     = b.x;
        g_AB[(base + 2 * p + 1) * 256 + ND + j] = b.y;
    }
}

// Edge kernel: 8 edges (4 packed pairs) per iteration, thread j owns column j.
__global__ void __launch_bounds__(128) k_edge(
    const float* __restrict__ ef, const int* __restrict__ ei,
    const float* __restrict__ W1, const float* __restrict__ b1,
    const float* __restrict__ lng, const float* __restrict__ lnb,
    const float* __restrict__ W2, const float* __restrict__ b2,
    const float* __restrict__ gw, const float* __restrict__ gb) {
    __shared__ __align__(16) float sefp[4][ED * 2];   // [pair][k*2+half]
    __shared__ __align__(16) float shp[4][ND * 2];    // [pair][j*2+half]
    __shared__ u64 sred[2][4][4];                     // [sum|sq][warp][pair]
    __shared__ float sgate[8];
    int j = threadIdx.x, lane = j & 31, w = j >> 5;
    float bj1 = b1[j], bj2 = b2[j], gsc = lng[j], gbi = lnb[j], gb0 = gb[0];
    const float* Wc1 = W1 + 256 * ND + j;
    const float* Wc2 = W2 + j;

    for (int e0 = blockIdx.x * 8; e0 < NE; e0 += gridDim.x * 8) {
        int4 s0 = *(const int4*)&ei[e0];
        int4 s1 = *(const int4*)&ei[e0 + 4];
        int4 d0 = *(const int4*)&ei[NE + e0];
        int4 d1 = *(const int4*)&ei[NE + e0 + 4];
        int src[8] = {s0.x, s0.y, s0.z, s0.w, s1.x, s1.y, s1.z, s1.w};
        int dst[8] = {d0.x, d0.y, d0.z, d0.w, d1.x, d1.y, d1.z, d1.w};
        {   // stage 8x64 edge features, pair-packed
            float4 v = ((const float4*)ef)[e0 * (ED / 4) + j];
            int e = j >> 4, k0 = (j & 15) * 4, h = e & 1, p = e >> 1;
            sefp[p][(k0 + 0) * 2 + h] = v.x;
            sefp[p][(k0 + 1) * 2 + h] = v.y;
            sefp[p][(k0 + 2) * 2 + h] = v.z;
            sefp[p][(k0 + 3) * 2 + h] = v.w;
        }
        __syncthreads();

        // gate: computed ONCE per edge (8 threads each), not by all 128
        if (j < 64) {
            int e = j >> 3, part = j & 7, h = e & 1, p = e >> 1;
            float acc = 0.f;
            #pragma unroll
            for (int q = 0; q < 8; q++) {
                int k = part * 8 + q;
                acc = fmaf(sefp[p][k * 2 + h], gw[k], acc);
            }
            acc += __shfl_down_sync(0xffffffffu, acc, 4, 8);
            acc += __shfl_down_sync(0xffffffffu, acc, 2, 8);
            acc += __shfl_down_sync(0xffffffffu, acc, 1, 8);
            if (part == 0) sgate[e] = fsig(acc + gb0);
        }

        // h = b1 + ef@W1c   (packed pairs, FFMA2)
        u64 hp[4];
        u64 b1p = pk(bj1, bj1);
        #pragma unroll
        for (int p = 0; p < 4; p++) hp[p] = b1p;
        #pragma unroll 4
        for (int k = 0; k < ED; k += 2) {
            float w0 = Wc1[k * ND], w1 = Wc1[(k + 1) * ND];
            u64 w0p = pk(w0, w0), w1p = pk(w1, w1);
            #pragma unroll
            for (int p = 0; p < 4; p++) {
                ulonglong2 xx = *(const ulonglong2*)&(((const u64*)sefp[p])[k]);
                hp[p] = fma2(xx.x, w0p, hp[p]);
                hp[p] = fma2(xx.y, w1p, hp[p]);
            }
        }
        // + A[src] + B[dst]
        #pragma unroll
        for (int p = 0; p < 4; p++) {
            float a0 = g_AB[src[2 * p] * 256 + j]     + g_AB[dst[2 * p] * 256 + ND + j];
            float a1 = g_AB[src[2 * p + 1] * 256 + j] + g_AB[dst[2 * p + 1] * 256 + ND + j];
            hp[p] = add2(hp[p], pk(a0, a1));
        }

        // LayerNorm over 128 columns (packed reductions)
        u64 s_[4], s2_[4];
        #pragma unroll
        for (int p = 0; p < 4; p++) { s_[p] = hp[p]; s2_[p] = mul2(hp[p], hp[p]); }
        #pragma unroll
        for (int o = 16; o; o >>= 1) {
            #pragma unroll
            for (int p = 0; p < 4; p++) {
                s_[p]  = add2(s_[p],  __shfl_xor_sync(0xffffffffu, s_[p],  o));
                s2_[p] = add2(s2_[p], __shfl_xor_sync(0xffffffffu, s2_[p], o));
            }
        }
        if (lane == 0) {
            #pragma unroll
            for (int p = 0; p < 4; p++) { sred[0][w][p] = s_[p]; sred[1][w][p] = s2_[p]; }
        }
        __syncthreads();
        #pragma unroll
        for (int p = 0; p < 4; p++) {
            u64 ssp  = add2(add2(sred[0][0][p], sred[0][1][p]),
                            add2(sred[0][2][p], sred[0][3][p]));
            u64 ss2p = add2(add2(sred[1][0][p], sred[1][1][p]),
                            add2(sred[1][2][p], sred[1][3][p]));
            float2 ss = upk(ssp), ss2 = upk(ss2p), hv = upk(hp[p]);
            float mu0 = ss.x * (1.f / ND), mu1 = ss.y * (1.f / ND);
            float v0 = ss2.x * (1.f / ND) - mu0 * mu0;
            float v1 = ss2.y * (1.f / ND) - mu1 * mu1;
            float hn0 = fmaxf((hv.x - mu0) * rsqrtf(v0 + 1e-5f) * gsc + gbi, 0.f);
            float hn1 = fmaxf((hv.y - mu1) * rsqrtf(v1 + 1e-5f) * gsc + gbi, 0.f);
            *(float2*)&shp[p][j * 2] = make_float2(hn0, hn1);
        }
        __syncthreads();

        // messages = relu(ln(h)) @ W2 + b2  (packed pairs, FFMA2)
        u64 mp[4];
        u64 b2p = pk(bj2, bj2);
        #pragma unroll
        for (int p = 0; p < 4; p++) mp[p] = b2p;
        #pragma unroll 4
        for (int k = 0; k < ND; k += 2) {
            float w0 = Wc2[k * ND], w1 = Wc2[(k + 1) * ND];
            u64 w0p = pk(w0, w0), w1p = pk(w1, w1);
            #pragma unroll
            for (int p = 0; p < 4; p++) {
                ulonglong2 xx = *(const ulonglong2*)&(((const u64*)shp[p])[k]);
                mp[p] = fma2(xx.x, w0p, mp[p]);
                mp[p] = fma2(xx.y, w1p, mp[p]);
            }
        }
        #pragma unroll
        for (int p = 0; p < 4; p++) {
            float2 mv = upk(mp[p]);
            atomicAdd(&g_agg[dst[2 * p] * ND + j],     mv.x * sgate[2 * p]);
            atomicAdd(&g_agg[dst[2 * p + 1] * ND + j], mv.y * sgate[2 * p + 1]);
        }
        __syncthreads();
    }
}

// GRU: 8 nodes (4 packed pairs) per block; gi-loop reads agg only, gh-loop reads nf only
__global__ void __launch_bounds__(128) k_gru(const float* __restrict__ nf,
                                             const float* __restrict__ bih,
                                             const float* __restrict__ bhh,
                                             float* __restrict__ out) {
    __shared__ __align__(16) float sap[4][ND * 2], snp[4][ND * 2];
    int j = threadIdx.x;
    int base = blockIdx.x * 8;
    #pragma unroll
    for (int n = 0; n < 8; n++) {
        sap[n >> 1][j * 2 + (n & 1)] = g_agg[(base + n) * ND + j];
        snp[n >> 1][j * 2 + (n & 1)] = nf[(base + n) * ND + j];
    }
    __syncthreads();
    u64 gi0[4], gi1[4], gi2[4], gh0[4], gh1[4], gh2[4];
    {
        u64 b0 = pk(bih[j], bih[j]), b1_ = pk(bih[ND + j], bih[ND + j]),
            b2_ = pk(bih[2 * ND + j], bih[2 * ND + j]);
        u64 c0 = pk(bhh[j], bhh[j]), c1 = pk(bhh[ND + j], bhh[ND + j]),
            c2 = pk(bhh[2 * ND + j], bhh[2 * ND + j]);
        #pragma unroll
        for (int p = 0; p < 4; p++) {
            gi0[p] = b0; gi1[p] = b1_; gi2[p] = b2_;
            gh0[p] = c0; gh1[p] = c1;  gh2[p] = c2;
        }
    }
    #pragma unroll 2
    for (int k = 0; k < ND; k += 2) {
        float wi00 = g_WtI[k * 384 + j],        wi01 = g_WtI[(k + 1) * 384 + j];
        float wi10 = g_WtI[k * 384 + ND + j],   wi11 = g_WtI[(k + 1) * 384 + ND + j];
        float wi20 = g_WtI[k * 384 + 2*ND + j], wi21 = g_WtI[(k + 1) * 384 + 2*ND + j];
        u64 a0 = pk(wi00, wi00), a1 = pk(wi01, wi01);
        u64 b0 = pk(wi10, wi10), b1_ = pk(wi11, wi11);
        u64 c0 = pk(wi20, wi20), c1 = pk(wi21, wi21);
        #pragma unroll
        for (int p = 0; p < 4; p++) {
            ulonglong2 xx = *(const ulonglong2*)&(((const u64*)sap[p])[k]);
            gi0[p] = fma2(xx.x, a0, gi0[p]); gi0[p] = fma2(xx.y, a1, gi0[p]);
            gi1[p] = fma2(xx.x, b0, gi1[p]); gi1[p] = fma2(xx.y, b1_, gi1[p]);
            gi2[p] = fma2(xx.x, c0, gi2[p]); gi2[p] = fma2(xx.y, c1, gi2[p]);
        }
    }
    #pragma unroll 2
    for (int k = 0; k < ND; k += 2) {
        float wh00 = g_WtH[k * 384 + j],        wh01 = g_WtH[(k + 1) * 384 + j];
        float wh10 = g_WtH[k * 384 + ND + j],   wh11 = g_WtH[(k + 1) * 384 + ND + j];
        float wh20 = g_WtH[k * 384 + 2*ND + j], wh21 = g_WtH[(k + 1) * 384 + 2*ND + j];
        u64 a0 = pk(wh00, wh00), a1 = pk(wh01, wh01);
        u64 b0 = pk(wh10, wh10), b1_ = pk(wh11, wh11);
        u64 c0 = pk(wh20, wh20), c1 = pk(wh21, wh21);
        #pragma unroll
        for (int p = 0; p < 4; p++) {
            ulonglong2 xx = *(const ulonglong2*)&(((const u64*)snp[p])[k]);
            gh0[p] = fma2(xx.x, a0, gh0[p]); gh0[p] = fma2(xx.y, a1, gh0[p]);
            gh1[p] = fma2(xx.x, b0, gh1[p]); gh1[p] = fma2(xx.y, b1_, gh1[p]);
            gh2[p] = fma2(xx.x, c0, gh2[p]); gh2[p] = fma2(xx.y, c1, gh2[p]);
        }
    }
    #pragma unroll
    for (int p = 0; p < 4; p++) {
        float2 i0 = upk(gi0[p]), i1 = upk(gi1[p]), i2 = upk(gi2[p]);
        float2 h0 = upk(gh0[p]), h1 = upk(gh1[p]), h2 = upk(gh2[p]);
        float r0 = fsig(i0.x + h0.x), r1 = fsig(i0.y + h0.y);
        float z0 = fsig(i1.x + h1.x), z1 = fsig(i1.y + h1.y);
        float n0 = ftanh(i2.x + r0 * h2.x), n1 = ftanh(i2.y + r1 * h2.y);
        out[(base + 2 * p) * ND + j]     = (1.f - z0) * n0 + z0 * snp[p][j * 2];
        out[(base + 2 * p + 1) * ND + j] = (1.f - z1) * n1 + z1 * snp[p][j * 2 + 1];
    }
}

extern "C" void kernel_launch(void* const* d_in, const int* in_sizes, int n_in,
                              void* d_out, int out_size) {
    const float* nf  = (const float*)d_in[0];
    const int*   ei  = (const int*)d_in[1];
    const float* ef  = (const float*)d_in[2];
    const float* W1  = (const float*)d_in[3];
    const float* b1  = (const float*)d_in[4];
    const float* lng = (const float*)d_in[5];
    const float* lnb = (const float*)d_in[6];
    const float* W2  = (const float*)d_in[7];
    const float* b2  = (const float*)d_in[8];
    const float* gw  = (const float*)d_in[9];
    const float* gb  = (const float*)d_in[10];
    const float* Wih = (const float*)d_in[11];
    const float* bih = (const float*)d_in[12];
    const float* Whh = (const float*)d_in[13];
    const float* bhh = (const float*)d_in[14];
    float* out = (float*)d_out;

    k_zero<<<(NN * ND / 4 + 255) / 256, 256>>>();
    k_transpose<<<(384 * ND + 255) / 256, 256>>>(Wih, Whh);
    k_nodeAB<<<NN / 8, 128>>>(nf, W1);
    k_edge<<<1184, 128>>>(ef, ei, W1, b1, lng, lnb, W2, b2, gw, gb);
    k_gru<<<NN / 8, 128>>>(nf, bih, bhh, out);
}

// round 3
// speedup vs baseline: 2.4116x; 1.8883x over previous
#include <cuda_runtime.h>

#define NN 40000
#define NE 640000
#define ND 128
#define ED 64

typedef unsigned long long u64;

// Scratch (static device allocations — allowed)
__device__ float g_AB[NN * 256];      // per-node A|B = nf@W1a | nf@W1b
__device__ float g_P[NN * ND];        // scatter target: sum of gate*relu(ln(h))
__device__ float g_G[NN];             // scatter target: sum of gates
__device__ float g_WtH[ND * 384];     // W_hh transposed [k][m]
__device__ float g_Wf[ND * 384];      // Wfold[q][m] = sum_k W2[q][k]*W_ih[m][k]
__device__ float g_bf[384];           // bfold[m]    = sum_k b2[k]  *W_ih[m][k]

// ---- packed f32x2 helpers (sm_103a dual-fp32 pipe) ----
__device__ __forceinline__ u64 pk(float a, float b) {
    u64 d; asm("mov.b64 %0, {%1,%2};" : "=l"(d)
               : "r"(__float_as_uint(a)), "r"(__float_as_uint(b)));
    return d;
}
__device__ __forceinline__ float2 upk(u64 v) {
    unsigned a, b; asm("mov.b64 {%0,%1}, %2;" : "=r"(a), "=r"(b) : "l"(v));
    return make_float2(__uint_as_float(a), __uint_as_float(b));
}
__device__ __forceinline__ u64 fma2(u64 a, u64 b, u64 c) {
    u64 d; asm("fma.rn.f32x2 %0, %1, %2, %3;" : "=l"(d) : "l"(a), "l"(b), "l"(c));
    return d;
}
__device__ __forceinline__ u64 add2(u64 a, u64 b) {
    u64 d; asm("add.rn.f32x2 %0, %1, %2;" : "=l"(d) : "l"(a), "l"(b));
    return d;
}
__device__ __forceinline__ u64 mul2(u64 a, u64 b) {
    u64 d; asm("mul.rn.f32x2 %0, %1, %2;" : "=l"(d) : "l"(a), "l"(b));
    return d;
}
__device__ __forceinline__ float fsig(float x) { return 1.f / (1.f + __expf(-x)); }
__device__ __forceinline__ float ftanh(float x) {
    float e = __expf(2.f * fabsf(x));
    return copysignf(1.f - 2.f / (e + 1.f), x);
}

__global__ void k_zero() {
    int i = blockIdx.x * blockDim.x + threadIdx.x;
    if (i < NN * ND / 4)
        reinterpret_cast<float4*>(g_P)[i] = make_float4(0.f, 0.f, 0.f, 0.f);
    if (i < NN / 4)
        reinterpret_cast<float4*>(g_G)[i] = make_float4(0.f, 0.f, 0.f, 0.f);
}

__global__ void k_transH(const float* __restrict__ Whh) {
    int idx = blockIdx.x * blockDim.x + threadIdx.x;
    if (idx < 384 * ND) {
        int k = idx / 384, m = idx % 384;
        g_WtH[idx] = Whh[m * ND + k];
    }
}

// Fold W2 into GRU input weights: Wfold[q][m] = sum_k W2[q][k]*Wih[m][k]
__global__ void __launch_bounds__(384) k_fold(const float* __restrict__ W2,
                                              const float* __restrict__ Wih,
                                              const float* __restrict__ b2) {
    __shared__ float sw[ND], sb[ND];
    int q = blockIdx.x, m = threadIdx.x;
    if (m < ND) { sw[m] = W2[q * ND + m]; sb[m] = b2[m]; }
    __syncthreads();
    float acc = 0.f, accb = 0.f;
    const float* wr = Wih + m * ND;
    #pragma unroll 4
    for (int k = 0; k < ND; k++) {
        float w = wr[k];
        acc  = fmaf(sw[k], w, acc);
        accb = fmaf(sb[k], w, accb);
    }
    g_Wf[q * 384 + m] = acc;
    if (q == 0) g_bf[m] = accb;
}

// A|B = nf @ [W1a | W1b], 8 nodes (4 packed pairs) per block
__global__ void __launch_bounds__(128) k_nodeAB(const float* __restrict__ nf,
                                                const float* __restrict__ W1) {
    __shared__ __align__(16) float sxp[4][ND * 2];
    int j = threadIdx.x;
    int base = blockIdx.x * 8;
    #pragma unroll
    for (int n = 0; n < 8; n++)
        sxp[n >> 1][j * 2 + (n & 1)] = nf[(base + n) * ND + j];
    __syncthreads();
    u64 accA[4] = {0, 0, 0, 0}, accB[4] = {0, 0, 0, 0};
    #pragma unroll 2
    for (int k = 0; k < ND; k += 2) {
        float wa0 = W1[k * ND + j], wa1 = W1[(k + 1) * ND + j];
        float wb0 = W1[(ND + k) * ND + j], wb1 = W1[(ND + k + 1) * ND + j];
        u64 wa0p = pk(wa0, wa0), wa1p = pk(wa1, wa1);
        u64 wb0p = pk(wb0, wb0), wb1p = pk(wb1, wb1);
        #pragma unroll
        for (int p = 0; p < 4; p++) {
            ulonglong2 xx = *(const ulonglong2*)&(((const u64*)sxp[p])[k]);
            accA[p] = fma2(xx.x, wa0p, accA[p]);
            accA[p] = fma2(xx.y, wa1p, accA[p]);
            accB[p] = fma2(xx.x, wb0p, accB[p]);
            accB[p] = fma2(xx.y, wb1p, accB[p]);
        }
    }
    #pragma unroll
    for (int p = 0; p < 4; p++) {
        float2 a = upk(accA[p]), b = upk(accB[p]);
        g_AB[(base + 2 * p) * 256 + j]          = a.x;
        g_AB[(base + 2 * p + 1) * 256 + j]      = a.y;
        g_AB[(base + 2 * p) * 256 + ND + j]     = b.x;
        g_AB[(base + 2 * p + 1) * 256 + ND + j] = b.y;
    }
}

// Edge kernel: 16 edges (8 packed pairs) per iteration, thread j owns column j.
// Only layer-1 GEMM remains per-edge; scatter gate*relu(ln(h)) into P, gate into G.
__global__ void __launch_bounds__(128) k_edge(
    const float* __restrict__ ef, const int* __restrict__ ei,
    const float* __restrict__ W1, const float* __restrict__ b1,
    const float* __restrict__ lng, const float* __restrict__ lnb,
    const float* __restrict__ gw, const float* __restrict__ gb) {
    __shared__ __align__(16) float sefp[8][ED * 2];   // [pair][k*2+half]
    __shared__ u64 sred[2][4][8];                     // [sum|sq][warp][pair]
    __shared__ float sgate[16];
    int j = threadIdx.x, lane = j & 31, w = j >> 5;
    float bj1 = b1[j], gsc = lng[j], gbi = lnb[j], gb0 = gb[0];
    const float* Wc1 = W1 + 256 * ND + j;

    for (int e0 = blockIdx.x * 16; e0 < NE; e0 += gridDim.x * 16) {
        int dst[16];
        u64 hp[8];
        {
            int4 s[2], d[2];
            s[0] = *(const int4*)&ei[e0];      s[1] = *(const int4*)&ei[e0 + 4];
            int4 s2 = *(const int4*)&ei[e0 + 8], s3 = *(const int4*)&ei[e0 + 12];
            d[0] = *(const int4*)&ei[NE + e0]; d[1] = *(const int4*)&ei[NE + e0 + 4];
            int4 d2 = *(const int4*)&ei[NE + e0 + 8], d3 = *(const int4*)&ei[NE + e0 + 12];
            int src[16] = {s[0].x, s[0].y, s[0].z, s[0].w, s[1].x, s[1].y, s[1].z, s[1].w,
                           s2.x, s2.y, s2.z, s2.w, s3.x, s3.y, s3.z, s3.w};
            dst[0] = d[0].x; dst[1] = d[0].y; dst[2] = d[0].z; dst[3] = d[0].w;
            dst[4] = d[1].x; dst[5] = d[1].y; dst[6] = d[1].z; dst[7] = d[1].w;
            dst[8] = d2.x; dst[9] = d2.y; dst[10] = d2.z; dst[11] = d2.w;
            dst[12] = d3.x; dst[13] = d3.y; dst[14] = d3.z; dst[15] = d3.w;
            // h init = b1 + A[src] + B[dst]  (frees src registers early)
            u64 b1p = pk(bj1, bj1);
            #pragma unroll
            for (int p = 0; p < 8; p++) {
                float a0 = g_AB[src[2 * p] * 256 + j]     + g_AB[dst[2 * p] * 256 + ND + j];
                float a1 = g_AB[src[2 * p + 1] * 256 + j] + g_AB[dst[2 * p + 1] * 256 + ND + j];
                hp[p] = add2(b1p, pk(a0, a1));
            }
        }
        {   // stage 16x64 edge features, pair-packed (2 float4 per thread)
            #pragma unroll
            for (int t = 0; t < 2; t++) {
                int fi = t * 128 + j;
                int e = fi >> 4, k0 = (fi & 15) * 4, h = e & 1, p = e >> 1;
                float4 v = ((const float4*)ef)[e0 * (ED / 4) + fi];
                sefp[p][(k0 + 0) * 2 + h] = v.x;
                sefp[p][(k0 + 1) * 2 + h] = v.y;
                sefp[p][(k0 + 2) * 2 + h] = v.z;
                sefp[p][(k0 + 3) * 2 + h] = v.w;
            }
        }
        __syncthreads();

        // gate: one edge per 8 threads (all 128 threads busy)
        {
            int e = j >> 3, part = j & 7, h = e & 1, p = e >> 1;
            float acc = 0.f;
            #pragma unroll
            for (int q = 0; q < 8; q++) {
                int k = part * 8 + q;
                acc = fmaf(sefp[p][k * 2 + h], gw[k], acc);
            }
            acc += __shfl_down_sync(0xffffffffu, acc, 4, 8);
            acc += __shfl_down_sync(0xffffffffu, acc, 2, 8);
            acc += __shfl_down_sync(0xffffffffu, acc, 1, 8);
            if (part == 0) sgate[e] = fsig(acc + gb0);
        }

        // h += ef @ W1c   (packed pairs, FFMA2)
        #pragma unroll 4
        for (int k = 0; k < ED; k += 2) {
            float w0 = Wc1[k * ND], w1 = Wc1[(k + 1) * ND];
            u64 w0p = pk(w0, w0), w1p = pk(w1, w1);
            #pragma unroll
            for (int p = 0; p < 8; p++) {
                ulonglong2 xx = *(const ulonglong2*)&(((const u64*)sefp[p])[k]);
                hp[p] = fma2(xx.x, w0p, hp[p]);
                hp[p] = fma2(xx.y, w1p, hp[p]);
            }
        }

        // LayerNorm over 128 columns (packed reductions)
        u64 s_[8], s2_[8];
        #pragma unroll
        for (int p = 0; p < 8; p++) { s_[p] = hp[p]; s2_[p] = mul2(hp[p], hp[p]); }
        #pragma unroll
        for (int o = 16; o; o >>= 1) {
            #pragma unroll
            for (int p = 0; p < 8; p++) {
                s_[p]  = add2(s_[p],  __shfl_xor_sync(0xffffffffu, s_[p],  o));
                s2_[p] = add2(s2_[p], __shfl_xor_sync(0xffffffffu, s2_[p], o));
            }
        }
        if (lane == 0) {
            #pragma unroll
            for (int p = 0; p < 8; p++) { sred[0][w][p] = s_[p]; sred[1][w][p] = s2_[p]; }
        }
        __syncthreads();

        // normalize, relu, gate, scatter-add into P
        #pragma unroll
        for (int p = 0; p < 8; p++) {
            u64 ssp  = add2(add2(sred[0][0][p], sred[0][1][p]),
                            add2(sred[0][2][p], sred[0][3][p]));
            u64 ss2p = add2(add2(sred[1][0][p], sred[1][1][p]),
                            add2(sred[1][2][p], sred[1][3][p]));
            float2 ss = upk(ssp), ss2 = upk(ss2p), hv = upk(hp[p]);
            float mu0 = ss.x * (1.f / ND), mu1 = ss.y * (1.f / ND);
            float v0 = ss2.x * (1.f / ND) - mu0 * mu0;
            float v1 = ss2.y * (1.f / ND) - mu1 * mu1;
            float hn0 = fmaxf((hv.x - mu0) * rsqrtf(v0 + 1e-5f) * gsc + gbi, 0.f);
            float hn1 = fmaxf((hv.y - mu1) * rsqrtf(v1 + 1e-5f) * gsc + gbi, 0.f);
            atomicAdd(&g_P[dst[2 * p] * ND + j],     hn0 * sgate[2 * p]);
            atomicAdd(&g_P[dst[2 * p + 1] * ND + j], hn1 * sgate[2 * p + 1]);
        }
        if (j < 16) atomicAdd(&g_G[dst[j]], sgate[j]);
        __syncthreads();
    }
}

// GRU with folded W2: gi = P@Wfold + G*bfold + b_ih; gh = nf@WtH + b_hh
__global__ void __launch_bounds__(128) k_gru(const float* __restrict__ nf,
                                             const float* __restrict__ bih,
                                             const float* __restrict__ bhh,
                                             float* __restrict__ out) {
    __shared__ __align__(16) float sap[4][ND * 2], snp[4][ND * 2];
    int j = threadIdx.x;
    int base = blockIdx.x * 8;
    #pragma unroll
    for (int n = 0; n < 8; n++) {
        sap[n >> 1][j * 2 + (n & 1)] = g_P[(base + n) * ND + j];
        snp[n >> 1][j * 2 + (n & 1)] = nf[(base + n) * ND + j];
    }
    __syncthreads();
    u64 gi0[4], gi1[4], gi2[4], gh0[4], gh1[4], gh2[4];
    {
        u64 b0 = pk(bih[j], bih[j]), b1_ = pk(bih[ND + j], bih[ND + j]),
            b2_ = pk(bih[2 * ND + j], bih[2 * ND + j]);
        u64 c0 = pk(bhh[j], bhh[j]), c1 = pk(bhh[ND + j], bhh[ND + j]),
            c2 = pk(bhh[2 * ND + j], bhh[2 * ND + j]);
        float bf0 = g_bf[j], bf1 = g_bf[ND + j], bf2 = g_bf[2 * ND + j];
        #pragma unroll
        for (int p = 0; p < 4; p++) {
            u64 gp = pk(g_G[base + 2 * p], g_G[base + 2 * p + 1]);
            gi0[p] = fma2(gp, pk(bf0, bf0), b0);
            gi1[p] = fma2(gp, pk(bf1, bf1), b1_);
            gi2[p] = fma2(gp, pk(bf2, bf2), b2_);
            gh0[p] = c0; gh1[p] = c1;  gh2[p] = c2;
        }
    }
    #pragma unroll 2
    for (int k = 0; k < ND; k += 2) {
        float wi00 = g_Wf[k * 384 + j],        wi01 = g_Wf[(k + 1) * 384 + j];
        float wi10 = g_Wf[k * 384 + ND + j],   wi11 = g_Wf[(k + 1) * 384 + ND + j];
        float wi20 = g_Wf[k * 384 + 2*ND + j], wi21 = g_Wf[(k + 1) * 384 + 2*ND + j];
        u64 a0 = pk(wi00, wi00), a1 = pk(wi01, wi01);
        u64 b0 = pk(wi10, wi10), b1_ = pk(wi11, wi11);
        u64 c0 = pk(wi20, wi20), c1 = pk(wi21, wi21);
        #pragma unroll
        for (int p = 0; p < 4; p++) {
            ulonglong2 xx = *(const ulonglong2*)&(((const u64*)sap[p])[k]);
            gi0[p] = fma2(xx.x, a0, gi0[p]); gi0[p] = fma2(xx.y, a1, gi0[p]);
            gi1[p] = fma2(xx.x, b0, gi1[p]); gi1[p] = fma2(xx.y, b1_, gi1[p]);
            gi2[p] = fma2(xx.x, c0, gi2[p]); gi2[p] = fma2(xx.y, c1, gi2[p]);
        }
    }
    #pragma unroll 2
    for (int k = 0; k < ND; k += 2) {
        float wh00 = g_WtH[k * 384 + j],        wh01 = g_WtH[(k + 1) * 384 + j];
        float wh10 = g_WtH[k * 384 + ND + j],   wh11 = g_WtH[(k + 1) * 384 + ND + j];
        float wh20 = g_WtH[k * 384 + 2*ND + j], wh21 = g_WtH[(k + 1) * 384 + 2*ND + j];
        u64 a0 = pk(wh00, wh00), a1 = pk(wh01, wh01);
        u64 b0 = pk(wh10, wh10), b1_ = pk(wh11, wh11);
        u64 c0 = pk(wh20, wh20), c1 = pk(wh21, wh21);
        #pragma unroll
        for (int p = 0; p < 4; p++) {
            ulonglong2 xx = *(const ulonglong2*)&(((const u64*)snp[p])[k]);
            gh0[p] = fma2(xx.x, a0, gh0[p]); gh0[p] = fma2(xx.y, a1, gh0[p]);
            gh1[p] = fma2(xx.x, b0, gh1[p]); gh1[p] = fma2(xx.y, b1_, gh1[p]);
            gh2[p] = fma2(xx.x, c0, gh2[p]); gh2[p] = fma2(xx.y, c1, gh2[p]);
        }
    }
    #pragma unroll
    for (int p = 0; p < 4; p++) {
        float2 i0 = upk(gi0[p]), i1 = upk(gi1[p]), i2 = upk(gi2[p]);
        float2 h0 = upk(gh0[p]), h1 = upk(gh1[p]), h2 = upk(gh2[p]);
        float r0 = fsig(i0.x + h0.x), r1 = fsig(i0.y + h0.y);
        float z0 = fsig(i1.x + h1.x), z1 = fsig(i1.y + h1.y);
        float n0 = ftanh(i2.x + r0 * h2.x), n1 = ftanh(i2.y + r1 * h2.y);
        out[(base + 2 * p) * ND + j]     = (1.f - z0) * n0 + z0 * snp[p][j * 2];
        out[(base + 2 * p + 1) * ND + j] = (1.f - z1) * n1 + z1 * snp[p][j * 2 + 1];
    }
}

extern "C" void kernel_launch(void* const* d_in, const int* in_sizes, int n_in,
                              void* d_out, int out_size) {
    const float* nf  = (const float*)d_in[0];
    const int*   ei  = (const int*)d_in[1];
    const float* ef  = (const float*)d_in[2];
    const float* W1  = (const float*)d_in[3];
    const float* b1  = (const float*)d_in[4];
    const float* lng = (const float*)d_in[5];
    const float* lnb = (const float*)d_in[6];
    const float* W2  = (const float*)d_in[7];
    const float* b2  = (const float*)d_in[8];
    const float* gw  = (const float*)d_in[9];
    const float* gb  = (const float*)d_in[10];
    const float* Wih = (const float*)d_in[11];
    const float* bih = (const float*)d_in[12];
    const float* Whh = (const float*)d_in[13];
    const float* bhh = (const float*)d_in[14];
    float* out = (float*)d_out;

    k_zero<<<(NN * ND / 4 + 255) / 256, 256>>>();
    k_transH<<<(384 * ND + 255) / 256, 256>>>(Whh);
    k_fold<<<ND, 384>>>(W2, Wih, b2);
    k_nodeAB<<<NN / 8, 128>>>(nf, W1);
    k_edge<<<2368, 128>>>(ef, ei, W1, b1, lng, lnb, gw, gb);
    k_gru<<<NN / 8, 128>>>(nf, bih, bhh, out);
}

// round 4
// speedup vs baseline: 3.0352x; 1.2586x over previous
#include <cuda_runtime.h>

#define NN 40000
#define NE 640000
#define ND 128
#define ED 64

typedef unsigned long long u64;

// Scratch (static device allocations — allowed)
__device__ float g_AB[NN * 256];      // per-node A|B = nf@W1a | nf@W1b
__device__ float g_P[NN * ND];        // scatter target: sum of gate*relu(ln(h))
__device__ float g_G[NN];             // scatter target: sum of gates
__device__ float g_WtH[ND * 384];     // W_hh transposed [k][m]
__device__ float g_Wf[ND * 384];      // Wfold[q][m] = sum_k W2[q][k]*W_ih[m][k]
__device__ float g_bf[384];           // bfold[m]    = sum_k b2[k]  *W_ih[m][k]

// ---- packed f32x2 helpers ----
__device__ __forceinline__ u64 pk(float a, float b) {
    u64 d; asm("mov.b64 %0, {%1,%2};" : "=l"(d)
               : "r"(__float_as_uint(a)), "r"(__float_as_uint(b)));
    return d;
}
__device__ __forceinline__ float2 upk(u64 v) {
    unsigned a, b; asm("mov.b64 {%0,%1}, %2;" : "=r"(a), "=r"(b) : "l"(v));
    return make_float2(__uint_as_float(a), __uint_as_float(b));
}
__device__ __forceinline__ u64 fma2(u64 a, u64 b, u64 c) {
    u64 d; asm("fma.rn.f32x2 %0, %1, %2, %3;" : "=l"(d) : "l"(a), "l"(b), "l"(c));
    return d;
}
__device__ __forceinline__ u64 add2(u64 a, u64 b) {
    u64 d; asm("add.rn.f32x2 %0, %1, %2;" : "=l"(d) : "l"(a), "l"(b));
    return d;
}
__device__ __forceinline__ u64 mul2(u64 a, u64 b) {
    u64 d; asm("mul.rn.f32x2 %0, %1, %2;" : "=l"(d) : "l"(a), "l"(b));
    return d;
}
__device__ __forceinline__ void red2(float* p, float a, float b) {
    asm volatile("red.global.add.v2.f32 [%0], {%1, %2};" :: "l"(p), "f"(a), "f"(b) : "memory");
}
__device__ __forceinline__ float fsig(float x) { return 1.f / (1.f + __expf(-x)); }
__device__ __forceinline__ float ftanh(float x) {
    float e = __expf(2.f * fabsf(x));
    return copysignf(1.f - 2.f / (e + 1.f), x);
}

__global__ void k_zero() {
    int i = blockIdx.x * blockDim.x + threadIdx.x;
    if (i < NN * ND / 4)
        reinterpret_cast<float4*>(g_P)[i] = make_float4(0.f, 0.f, 0.f, 0.f);
    if (i < NN / 4)
        reinterpret_cast<float4*>(g_G)[i] = make_float4(0.f, 0.f, 0.f, 0.f);
}

__global__ void k_transH(const float* __restrict__ Whh) {
    int idx = blockIdx.x * blockDim.x + threadIdx.x;
    if (idx < 384 * ND) {
        int k = idx / 384, m = idx % 384;
        g_WtH[idx] = Whh[m * ND + k];
    }
}

// Fold W2 into GRU input weights: Wfold[q][m] = sum_k W2[q][k]*Wih[m][k]
__global__ void __launch_bounds__(384) k_fold(const float* __restrict__ W2,
                                              const float* __restrict__ Wih,
                                              const float* __restrict__ b2) {
    __shared__ float sw[ND], sb[ND];
    int q = blockIdx.x, m = threadIdx.x;
    if (m < ND) { sw[m] = W2[q * ND + m]; sb[m] = b2[m]; }
    __syncthreads();
    float acc = 0.f, accb = 0.f;
    const float* wr = Wih + m * ND;
    #pragma unroll 4
    for (int k = 0; k < ND; k++) {
        float w = wr[k];
        acc  = fmaf(sw[k], w, acc);
        accb = fmaf(sb[k], w, accb);
    }
    g_Wf[q * 384 + m] = acc;
    if (q == 0) g_bf[m] = accb;
}

// A|B = nf @ [W1a | W1b], 16 nodes (8 packed pairs) per block
__global__ void __launch_bounds__(128) k_nodeAB(const float* __restrict__ nf,
                                                const float* __restrict__ W1) {
    __shared__ __align__(16) float sxp[8][ND * 2];
    int j = threadIdx.x;
    int base = blockIdx.x * 16;
    #pragma unroll
    for (int n = 0; n < 16; n++)
        sxp[n >> 1][j * 2 + (n & 1)] = nf[(base + n) * ND + j];
    __syncthreads();
    u64 accA[8], accB[8];
    #pragma unroll
    for (int p = 0; p < 8; p++) { accA[p] = 0; accB[p] = 0; }
    #pragma unroll 2
    for (int k = 0; k < ND; k += 2) {
        float wa0 = W1[k * ND + j], wa1 = W1[(k + 1) * ND + j];
        float wb0 = W1[(ND + k) * ND + j], wb1 = W1[(ND + k + 1) * ND + j];
        u64 wa0p = pk(wa0, wa0), wa1p = pk(wa1, wa1);
        u64 wb0p = pk(wb0, wb0), wb1p = pk(wb1, wb1);
        #pragma unroll
        for (int p = 0; p < 8; p++) {
            ulonglong2 xx = *(const ulonglong2*)&(((const u64*)sxp[p])[k]);
            accA[p] = fma2(xx.x, wa0p, accA[p]);
            accA[p] = fma2(xx.y, wa1p, accA[p]);
            accB[p] = fma2(xx.x, wb0p, accB[p]);
            accB[p] = fma2(xx.y, wb1p, accB[p]);
        }
    }
    #pragma unroll
    for (int p = 0; p < 8; p++) {
        float2 a = upk(accA[p]), b = upk(accB[p]);
        g_AB[(base + 2 * p) * 256 + j]          = a.x;
        g_AB[(base + 2 * p + 1) * 256 + j]      = a.y;
        g_AB[(base + 2 * p) * 256 + ND + j]     = b.x;
        g_AB[(base + 2 * p + 1) * 256 + ND + j] = b.y;
    }
}

// Edge kernel: 16 edges/tile. Warp layout: pg = warp>>1 picks pairs (4 of 8),
// cg = warp&1 picks column half; each thread owns 2 adjacent columns.
// Each LDS.128 broadcast feeds 4 FFMA2.
__global__ void __launch_bounds__(128) k_edge(
    const float* __restrict__ ef, const int* __restrict__ ei,
    const float* __restrict__ W1, const float* __restrict__ b1,
    const float* __restrict__ lng, const float* __restrict__ lnb,
    const float* __restrict__ gw, const float* __restrict__ gb) {
    __shared__ __align__(16) float sefp[8][ED * 2];   // [pair][k*2+half]
    __shared__ int sidx[32];                          // src[16] | dst[16]
    __shared__ u64 sred[2][2][2][4];                  // [s|s2][pg][cg][p]
    __shared__ float sgate[16];
    int t = threadIdx.x, l = t & 31, w = t >> 5;
    int cg = w & 1, pg = w >> 1;
    int j0 = cg * 64 + l * 2;
    float2 b1v  = *(const float2*)&b1[j0];
    float2 gscv = *(const float2*)&lng[j0];
    float2 gbiv = *(const float2*)&lnb[j0];
    float gb0 = gb[0];
    const float2* Wc = (const float2*)(W1 + 256 * ND) + (j0 >> 1);

    for (int e0 = blockIdx.x * 16; e0 < NE; e0 += gridDim.x * 16) {
        // stage edge indices + features
        if (t < 16) sidx[t] = ei[e0 + t];
        else if (t < 32) sidx[t] = ei[NE + e0 + (t - 16)];
        #pragma unroll
        for (int q = 0; q < 2; q++) {
            int fi = q * 128 + t;
            int e = fi >> 4, k0 = (fi & 15) * 4, h = e & 1, p = e >> 1;
            float4 v = ((const float4*)ef)[e0 * (ED / 4) + fi];
            sefp[p][(k0 + 0) * 2 + h] = v.x;
            sefp[p][(k0 + 1) * 2 + h] = v.y;
            sefp[p][(k0 + 2) * 2 + h] = v.z;
            sefp[p][(k0 + 3) * 2 + h] = v.w;
        }
        __syncthreads();

        // gate: one edge per 8 threads
        {
            int e = t >> 3, part = t & 7, h = e & 1, p = e >> 1;
            float acc = 0.f;
            #pragma unroll
            for (int q = 0; q < 8; q++) {
                int k = part * 8 + q;
                acc = fmaf(sefp[p][k * 2 + h], gw[k], acc);
            }
            acc += __shfl_down_sync(0xffffffffu, acc, 4, 8);
            acc += __shfl_down_sync(0xffffffffu, acc, 2, 8);
            acc += __shfl_down_sync(0xffffffffu, acc, 1, 8);
            if (part == 0) sgate[e] = fsig(acc + gb0);
        }

        // h init = b1 + A[src] + B[dst]   (acc0 = col j0, acc1 = col j0+1; lanes = 2 edges)
        u64 acc0[4], acc1[4];
        int myd[8];
        #pragma unroll
        for (int p = 0; p < 4; p++) {
            int P = pg * 4 + p;
            int s0 = sidx[2 * P], s1 = sidx[2 * P + 1];
            int d0 = sidx[16 + 2 * P], d1 = sidx[16 + 2 * P + 1];
            myd[2 * p] = d0; myd[2 * p + 1] = d1;
            float2 A0 = *(const float2*)&g_AB[s0 * 256 + j0];
            float2 A1 = *(const float2*)&g_AB[s1 * 256 + j0];
            float2 B0 = *(const float2*)&g_AB[d0 * 256 + ND + j0];
            float2 B1 = *(const float2*)&g_AB[d1 * 256 + ND + j0];
            acc0[p] = pk(A0.x + B0.x + b1v.x, A1.x + B1.x + b1v.x);
            acc1[p] = pk(A0.y + B0.y + b1v.y, A1.y + B1.y + b1v.y);
        }

        // h += ef @ W1c : 1 broadcast LDS.128 feeds 4 FFMA2
        #pragma unroll 4
        for (int k = 0; k < ED; k += 2) {
            float2 wk  = Wc[k * 64];
            float2 wk1 = Wc[(k + 1) * 64];
            u64 w00 = pk(wk.x,  wk.x),  w10 = pk(wk1.x, wk1.x);
            u64 w01 = pk(wk.y,  wk.y),  w11 = pk(wk1.y, wk1.y);
            #pragma unroll
            for (int p = 0; p < 4; p++) {
                ulonglong2 xx = *(const ulonglong2*)&(((const u64*)sefp[pg * 4 + p])[k]);
                acc0[p] = fma2(xx.x, w00, acc0[p]);
                acc0[p] = fma2(xx.y, w10, acc0[p]);
                acc1[p] = fma2(xx.x, w01, acc1[p]);
                acc1[p] = fma2(xx.y, w11, acc1[p]);
            }
        }

        // LayerNorm partial sums (2 cols pre-added), warp reduce over 32 lanes = 64 cols
        u64 s_[4], s2_[4];
        #pragma unroll
        for (int p = 0; p < 4; p++) {
            s_[p]  = add2(acc0[p], acc1[p]);
            s2_[p] = add2(mul2(acc0[p], acc0[p]), mul2(acc1[p], acc1[p]));
        }
        #pragma unroll
        for (int o = 16; o; o >>= 1) {
            #pragma unroll
            for (int p = 0; p < 4; p++) {
                s_[p]  = add2(s_[p],  __shfl_xor_sync(0xffffffffu, s_[p],  o));
                s2_[p] = add2(s2_[p], __shfl_xor_sync(0xffffffffu, s2_[p], o));
            }
        }
        if (l == 0) {
            #pragma unroll
            for (int p = 0; p < 4; p++) { sred[0][pg][cg][p] = s_[p]; sred[1][pg][cg][p] = s2_[p]; }
        }
        __syncthreads();

        // normalize, relu, gate, vector-reduce scatter into P
        #pragma unroll
        for (int p = 0; p < 4; p++) {
            float2 ss  = upk(add2(sred[0][pg][0][p], sred[0][pg][1][p]));
            float2 ss2 = upk(add2(sred[1][pg][0][p], sred[1][pg][1][p]));
            float mua = ss.x * (1.f / ND), mub = ss.y * (1.f / ND);
            float va = ss2.x * (1.f / ND) - mua * mua;
            float vb = ss2.y * (1.f / ND) - mub * mub;
            float ra = rsqrtf(va + 1e-5f), rb = rsqrtf(vb + 1e-5f);
            float2 h0 = upk(acc0[p]);   // (edge a, edge b) at col j0
            float2 h1 = upk(acc1[p]);   // at col j0+1
            int P = pg * 4 + p;
            float ga = sgate[2 * P], gbt = sgate[2 * P + 1];
            float a0 = fmaxf((h0.x - mua) * ra * gscv.x + gbiv.x, 0.f) * ga;
            float a1 = fmaxf((h1.x - mua) * ra * gscv.y + gbiv.y, 0.f) * ga;
            float b0_ = fmaxf((h0.y - mub) * rb * gscv.x + gbiv.x, 0.f) * gbt;
            float b1_ = fmaxf((h1.y - mub) * rb * gscv.y + gbiv.y, 0.f) * gbt;
            red2(&g_P[myd[2 * p] * ND + j0],     a0, a1);
            red2(&g_P[myd[2 * p + 1] * ND + j0], b0_, b1_);
        }
        if (t < 16) atomicAdd(&g_G[sidx[16 + t]], sgate[t]);
        __syncthreads();
    }
}

// GRU, 16 nodes/block (8 pairs). Phase1: gi = P@Wfold + G*bfold + b_ih -> smem.
// Phase2: gh = nf@WtH + b_hh in the SAME registers. Then combine.
__global__ void __launch_bounds__(128) k_gru(const float* __restrict__ nf,
                                             const float* __restrict__ bih,
                                             const float* __restrict__ bhh,
                                             float* __restrict__ out) {
    __shared__ __align__(16) float sap[8][ND * 2], snp[8][ND * 2];
    __shared__ u64 sgi[8][3][ND];
    int j = threadIdx.x;
    int base = blockIdx.x * 16;
    #pragma unroll
    for (int n = 0; n < 16; n++) {
        sap[n >> 1][j * 2 + (n & 1)] = g_P[(base + n) * ND + j];
        snp[n >> 1][j * 2 + (n & 1)] = nf[(base + n) * ND + j];
    }
    __syncthreads();
    u64 a0[8], a1[8], a2[8];
    // phase 1: gi
    {
        u64 b0 = pk(bih[j], bih[j]), b1_ = pk(bih[ND + j], bih[ND + j]),
            b2_ = pk(bih[2 * ND + j], bih[2 * ND + j]);
        float bf0 = g_bf[j], bf1 = g_bf[ND + j], bf2 = g_bf[2 * ND + j];
        #pragma unroll
        for (int p = 0; p < 8; p++) {
            u64 gp = pk(g_G[base + 2 * p], g_G[base + 2 * p + 1]);
            a0[p] = fma2(gp, pk(bf0, bf0), b0);
            a1[p] = fma2(gp, pk(bf1, bf1), b1_);
            a2[p] = fma2(gp, pk(bf2, bf2), b2_);
        }
    }
    #pragma unroll 2
    for (int k = 0; k < ND; k += 2) {
        float w00 = g_Wf[k * 384 + j],          w01 = g_Wf[(k + 1) * 384 + j];
        float w10 = g_Wf[k * 384 + ND + j],     w11 = g_Wf[(k + 1) * 384 + ND + j];
        float w20 = g_Wf[k * 384 + 2 * ND + j], w21 = g_Wf[(k + 1) * 384 + 2 * ND + j];
        u64 p00 = pk(w00, w00), p01 = pk(w01, w01);
        u64 p10 = pk(w10, w10), p11 = pk(w11, w11);
        u64 p20 = pk(w20, w20), p21 = pk(w21, w21);
        #pragma unroll
        for (int p = 0; p < 8; p++) {
            ulonglong2 xx = *(const ulonglong2*)&(((const u64*)sap[p])[k]);
            a0[p] = fma2(xx.x, p00, a0[p]); a0[p] = fma2(xx.y, p01, a0[p]);
            a1[p] = fma2(xx.x, p10, a1[p]); a1[p] = fma2(xx.y, p11, a1[p]);
            a2[p] = fma2(xx.x, p20, a2[p]); a2[p] = fma2(xx.y, p21, a2[p]);
        }
    }
    #pragma unroll
    for (int p = 0; p < 8; p++) {
        sgi[p][0][j] = a0[p]; sgi[p][1][j] = a1[p]; sgi[p][2][j] = a2[p];
    }
    // phase 2: gh (reuse registers)
    {
        u64 c0 = pk(bhh[j], bhh[j]), c1 = pk(bhh[ND + j], bhh[ND + j]),
            c2 = pk(bhh[2 * ND + j], bhh[2 * ND + j]);
        #pragma unroll
        for (int p = 0; p < 8; p++) { a0[p] = c0; a1[p] = c1; a2[p] = c2; }
    }
    #pragma unroll 2
    for (int k = 0; k < ND; k += 2) {
        float w00 = g_WtH[k * 384 + j],          w01 = g_WtH[(k + 1) * 384 + j];
        float w10 = g_WtH[k * 384 + ND + j],     w11 = g_WtH[(k + 1) * 384 + ND + j];
        float w20 = g_WtH[k * 384 + 2 * ND + j], w21 = g_WtH[(k + 1) * 384 + 2 * ND + j];
        u64 p00 = pk(w00, w00), p01 = pk(w01, w01);
        u64 p10 = pk(w10, w10), p11 = pk(w11, w11);
        u64 p20 = pk(w20, w20), p21 = pk(w21, w21);
        #pragma unroll
        for (int p = 0; p < 8; p++) {
            ulonglong2 xx = *(const ulonglong2*)&(((const u64*)snp[p])[k]);
            a0[p] = fma2(xx.x, p00, a0[p]); a0[p] = fma2(xx.y, p01, a0[p]);
            a1[p] = fma2(xx.x, p10, a1[p]); a1[p] = fma2(xx.y, p11, a1[p]);
            a2[p] = fma2(xx.x, p20, a2[p]); a2[p] = fma2(xx.y, p21, a2[p]);
        }
    }
    // combine
    #pragma unroll
    for (int p = 0; p < 8; p++) {
        float2 i0 = upk(sgi[p][0][j]), i1 = upk(sgi[p][1][j]), i2 = upk(sgi[p][2][j]);
        float2 h0 = upk(a0[p]), h1 = upk(a1[p]), h2 = upk(a2[p]);
        float r0 = fsig(i0.x + h0.x), r1 = fsig(i0.y + h0.y);
        float z0 = fsig(i1.x + h1.x), z1 = fsig(i1.y + h1.y);
        float n0 = ftanh(i2.x + r0 * h2.x), n1 = ftanh(i2.y + r1 * h2.y);
        out[(base + 2 * p) * ND + j]     = (1.f - z0) * n0 + z0 * snp[p][j * 2];
        out[(base + 2 * p + 1) * ND + j] = (1.f - z1) * n1 + z1 * snp[p][j * 2 + 1];
    }
}

extern "C" void kernel_launch(void* const* d_in, const int* in_sizes, int n_in,
                              void* d_out, int out_size) {
    const float* nf  = (const float*)d_in[0];
    const int*   ei  = (const int*)d_in[1];
    const float* ef  = (const float*)d_in[2];
    const float* W1  = (const float*)d_in[3];
    const float* b1  = (const float*)d_in[4];
    const float* lng = (const float*)d_in[5];
    const float* lnb = (const float*)d_in[6];
    const float* W2  = (const float*)d_in[7];
    const float* b2  = (const float*)d_in[8];
    const float* gw  = (const float*)d_in[9];
    const float* gb  = (const float*)d_in[10];
    const float* Wih = (const float*)d_in[11];
    const float* bih = (const float*)d_in[12];
    const float* Whh = (const float*)d_in[13];
    const float* bhh = (const float*)d_in[14];
    float* out = (float*)d_out;

    k_zero<<<(NN * ND / 4 + 255) / 256, 256>>>();
    k_transH<<<(384 * ND + 255) / 256, 256>>>(Whh);
    k_fold<<<ND, 384>>>(W2, Wih, b2);
    k_nodeAB<<<NN / 16, 128>>>(nf, W1);
    k_edge<<<2368, 128>>>(ef, ei, W1, b1, lng, lnb, gw, gb);
    k_gru<<<NN / 16, 128>>>(nf, bih, bhh, out);
}

// round 6
// speedup vs baseline: 3.5590x; 1.1726x over previous
#include <cuda_runtime.h>

#define NN 40000
#define NE 640000
#define ND 128
#define ED 64

typedef unsigned long long u64;

// Scratch (static device allocations — allowed)
__device__ float g_AB[NN * 256];      // per-node A|B = nf@W1a | nf@W1b
__device__ float g_P[NN * ND];        // scatter target: sum of gate*relu(ln(h))
__device__ float g_G[NN];             // scatter target: sum of gates
__device__ float g_WtH[ND * 384];     // W_hh transposed [k][m]
__device__ float g_Wf[ND * 384];      // Wfold[q][m] = sum_k W2[q][k]*W_ih[m][k]
__device__ float g_bf[384];           // bfold[m]    = sum_k b2[k]  *W_ih[m][k]

// ---- packed f32x2 helpers ----
__device__ __forceinline__ u64 pk(float a, float b) {
    u64 d; asm("mov.b64 %0, {%1,%2};" : "=l"(d)
               : "r"(__float_as_uint(a)), "r"(__float_as_uint(b)));
    return d;
}
__device__ __forceinline__ float2 upk(u64 v) {
    unsigned a, b; asm("mov.b64 {%0,%1}, %2;" : "=r"(a), "=r"(b) : "l"(v));
    return make_float2(__uint_as_float(a), __uint_as_float(b));
}
__device__ __forceinline__ u64 fma2(u64 a, u64 b, u64 c) {
    u64 d; asm("fma.rn.f32x2 %0, %1, %2, %3;" : "=l"(d) : "l"(a), "l"(b), "l"(c));
    return d;
}
__device__ __forceinline__ u64 add2(u64 a, u64 b) {
    u64 d; asm("add.rn.f32x2 %0, %1, %2;" : "=l"(d) : "l"(a), "l"(b));
    return d;
}
__device__ __forceinline__ u64 mul2(u64 a, u64 b) {
    u64 d; asm("mul.rn.f32x2 %0, %1, %2;" : "=l"(d) : "l"(a), "l"(b));
    return d;
}
__device__ __forceinline__ void red4(float* p, float4 v) {
    asm volatile("red.global.add.v4.f32 [%0], {%1, %2, %3, %4};"
                 :: "l"(p), "f"(v.x), "f"(v.y), "f"(v.z), "f"(v.w) : "memory");
}
__device__ __forceinline__ float fsig(float x) { return 1.f / (1.f + __expf(-x)); }
__device__ __forceinline__ float ftanh(float x) {
    float e = __expf(2.f * fabsf(x));
    return copysignf(1.f - 2.f / (e + 1.f), x);
}

__global__ void k_zero() {
    int i = blockIdx.x * blockDim.x + threadIdx.x;
    if (i < NN * ND / 4)
        reinterpret_cast<float4*>(g_P)[i] = make_float4(0.f, 0.f, 0.f, 0.f);
    if (i < NN / 4)
        reinterpret_cast<float4*>(g_G)[i] = make_float4(0.f, 0.f, 0.f, 0.f);
}

__global__ void k_transH(const float* __restrict__ Whh) {
    int idx = blockIdx.x * blockDim.x + threadIdx.x;
    if (idx < 384 * ND) {
        int k = idx / 384, m = idx % 384;
        g_WtH[idx] = Whh[m * ND + k];
    }
}

// Fold W2 into GRU input weights
__global__ void __launch_bounds__(384) k_fold(const float* __restrict__ W2,
                                              const float* __restrict__ Wih,
                                              const float* __restrict__ b2) {
    __shared__ float sw[ND], sb[ND];
    int q = blockIdx.x, m = threadIdx.x;
    if (m < ND) { sw[m] = W2[q * ND + m]; sb[m] = b2[m]; }
    __syncthreads();
    float acc = 0.f, accb = 0.f;
    const float* wr = Wih + m * ND;
    #pragma unroll 4
    for (int k = 0; k < ND; k++) {
        float w = wr[k];
        acc  = fmaf(sw[k], w, acc);
        accb = fmaf(sb[k], w, accb);
    }
    g_Wf[q * 384 + m] = acc;
    if (q == 0) g_bf[m] = accb;
}

// A|B = nf @ [W1a | W1b], 16 nodes (8 packed pairs) per block
__global__ void __launch_bounds__(128) k_nodeAB(const float* __restrict__ nf,
                                                const float* __restrict__ W1) {
    __shared__ __align__(16) float sxp[8][ND * 2];
    int j = threadIdx.x;
    int base = blockIdx.x * 16;
    #pragma unroll
    for (int n = 0; n < 16; n++)
        sxp[n >> 1][j * 2 + (n & 1)] = nf[(base + n) * ND + j];
    __syncthreads();
    u64 accA[8], accB[8];
    #pragma unroll
    for (int p = 0; p < 8; p++) { accA[p] = 0; accB[p] = 0; }
    #pragma unroll 2
    for (int k = 0; k < ND; k += 2) {
        float wa0 = W1[k * ND + j], wa1 = W1[(k + 1) * ND + j];
        float wb0 = W1[(ND + k) * ND + j], wb1 = W1[(ND + k + 1) * ND + j];
        u64 wa0p = pk(wa0, wa0), wa1p = pk(wa1, wa1);
        u64 wb0p = pk(wb0, wb0), wb1p = pk(wb1, wb1);
        #pragma unroll
        for (int p = 0; p < 8; p++) {
            ulonglong2 xx = *(const ulonglong2*)&(((const u64*)sxp[p])[k]);
            accA[p] = fma2(xx.x, wa0p, accA[p]);
            accA[p] = fma2(xx.y, wa1p, accA[p]);
            accB[p] = fma2(xx.x, wb0p, accB[p]);
            accB[p] = fma2(xx.y, wb1p, accB[p]);
        }
    }
    #pragma unroll
    for (int p = 0; p < 8; p++) {
        float2 a = upk(accA[p]), b = upk(accB[p]);
        g_AB[(base + 2 * p) * 256 + j]          = a.x;
        g_AB[(base + 2 * p + 1) * 256 + j]      = a.y;
        g_AB[(base + 2 * p) * 256 + ND + j]     = b.x;
        g_AB[(base + 2 * p + 1) * 256 + ND + j] = b.y;
    }
}

// Edge kernel: warp-autonomous. Each warp: 16 edges (8 packed pairs) x 128 cols,
// 4 cols/thread. No block barriers; LN fully warp-local.
__global__ void __launch_bounds__(128, 4) k_edge(
    const float* __restrict__ ef, const int* __restrict__ ei,
    const float* __restrict__ W1, const float* __restrict__ b1,
    const float* __restrict__ lng, const float* __restrict__ lnb,
    const float* __restrict__ gw, const float* __restrict__ gb) {
    // per-warp staging: 8 pairs, stride 132 floats (pad kills gate-dot conflicts)
    __shared__ __align__(16) float sef[4][8 * 132];
    __shared__ float sg[4][16];
    int t = threadIdx.x, l = t & 31, w = t >> 5;
    float* mysef = sef[w];
    float4 b1v = *(const float4*)&b1[4 * l];
    float4 gv  = *(const float4*)&lng[4 * l];
    float4 bv  = *(const float4*)&lnb[4 * l];
    float gb0 = gb[0];
    const float4* WC = (const float4*)(W1 + 256 * ND) + l;   // row k at WC[k*32]

    for (int e0 = (blockIdx.x * 4 + w) * 16; e0 < NE; e0 += gridDim.x * 64) {
        __syncwarp();
        int sv = ei[e0 + (l & 15)];
        int dv = ei[NE + e0 + (l & 15)];
        // stage 16 edges pair-packed: [p][k*2+h], one STS.128 per slot
        #pragma unroll
        for (int q = 0; q < 8; q++) {
            float2 v0 = *(const float2*)&ef[(e0 + 2 * q) * ED + 2 * l];
            float2 v1 = *(const float2*)&ef[(e0 + 2 * q + 1) * ED + 2 * l];
            *(float4*)&mysef[q * 132 + 4 * l] = make_float4(v0.x, v1.x, v0.y, v1.y);
        }
        __syncwarp();

        // gate: 2 lanes per edge, 32 k each
        {
            int e = l >> 1, p = e >> 1, h = e & 1, k0 = (l & 1) * 32;
            const float* base = &mysef[p * 132 + h];
            float gd = 0.f;
            #pragma unroll
            for (int i = 0; i < 32; i++)
                gd = fmaf(base[(k0 + i) * 2], gw[k0 + i], gd);
            gd += __shfl_xor_sync(0xffffffffu, gd, 1);
            if ((l & 1) == 0) sg[w][e] = fsig(gd + gb0);
        }

        // acc init = b1 + A[src] + B[dst]  (4 cols/thread, pairs packed)
        u64 acc[8][4];
        #pragma unroll
        for (int p = 0; p < 8; p++) {
            int s0 = __shfl_sync(0xffffffffu, sv, 2 * p);
            int s1 = __shfl_sync(0xffffffffu, sv, 2 * p + 1);
            int d0 = __shfl_sync(0xffffffffu, dv, 2 * p);
            int d1 = __shfl_sync(0xffffffffu, dv, 2 * p + 1);
            float4 A0 = *(const float4*)&g_AB[s0 * 256 + 4 * l];
            float4 A1 = *(const float4*)&g_AB[s1 * 256 + 4 * l];
            float4 B0 = *(const float4*)&g_AB[d0 * 256 + ND + 4 * l];
            float4 B1 = *(const float4*)&g_AB[d1 * 256 + ND + 4 * l];
            acc[p][0] = pk(b1v.x + A0.x + B0.x, b1v.x + A1.x + B1.x);
            acc[p][1] = pk(b1v.y + A0.y + B0.y, b1v.y + A1.y + B1.y);
            acc[p][2] = pk(b1v.z + A0.z + B0.z, b1v.z + A1.z + B1.z);
            acc[p][3] = pk(b1v.w + A0.w + B0.w, b1v.w + A1.w + B1.w);
        }

        // h += ef @ W1c : one LDS.128 broadcast feeds 8 FFMA2 (4 cols x 2 k)
        #pragma unroll 1
        for (int k = 0; k < ED; k += 2) {
            float4 w0 = WC[k * 32];
            float4 w1 = WC[(k + 1) * 32];
            u64 w0x = pk(w0.x, w0.x), w0y = pk(w0.y, w0.y);
            u64 w0z = pk(w0.z, w0.z), w0w = pk(w0.w, w0.w);
            u64 w1x = pk(w1.x, w1.x), w1y = pk(w1.y, w1.y);
            u64 w1z = pk(w1.z, w1.z), w1w = pk(w1.w, w1.w);
            #pragma unroll
            for (int p = 0; p < 8; p++) {
                ulonglong2 xx = *(const ulonglong2*)&mysef[p * 132 + 2 * k];
                acc[p][0] = fma2(xx.x, w0x, acc[p][0]);
                acc[p][1] = fma2(xx.x, w0y, acc[p][1]);
                acc[p][2] = fma2(xx.x, w0z, acc[p][2]);
                acc[p][3] = fma2(xx.x, w0w, acc[p][3]);
                acc[p][0] = fma2(xx.y, w1x, acc[p][0]);
                acc[p][1] = fma2(xx.y, w1y, acc[p][1]);
                acc[p][2] = fma2(xx.y, w1z, acc[p][2]);
                acc[p][3] = fma2(xx.y, w1w, acc[p][3]);
            }
        }

        // warp-local LayerNorm stats (pre-add 4 cols)
        u64 sum[8], sq[8];
        #pragma unroll
        for (int p = 0; p < 8; p++) {
            sum[p] = add2(add2(acc[p][0], acc[p][1]), add2(acc[p][2], acc[p][3]));
            sq[p]  = add2(add2(mul2(acc[p][0], acc[p][0]), mul2(acc[p][1], acc[p][1])),
                          add2(mul2(acc[p][2], acc[p][2]), mul2(acc[p][3], acc[p][3])));
        }
        #pragma unroll
        for (int o = 16; o; o >>= 1) {
            #pragma unroll
            for (int p = 0; p < 8; p++) {
                sum[p] = add2(sum[p], __shfl_xor_sync(0xffffffffu, sum[p], o));
                sq[p]  = add2(sq[p],  __shfl_xor_sync(0xffffffffu, sq[p],  o));
            }
        }
        __syncwarp();

        // normalize, relu, gate, vectored reduce-scatter
        #pragma unroll
        for (int p = 0; p < 8; p++) {
            float2 s = upk(sum[p]), s2 = upk(sq[p]);
            float mu0 = s.x * (1.f / ND), mu1 = s.y * (1.f / ND);
            float r0 = rsqrtf(s2.x * (1.f / ND) - mu0 * mu0 + 1e-5f);
            float r1 = rsqrtf(s2.y * (1.f / ND) - mu1 * mu1 + 1e-5f);
            float g0 = sg[w][2 * p], g1 = sg[w][2 * p + 1];
            int d0 = __shfl_sync(0xffffffffu, dv, 2 * p);
            int d1 = __shfl_sync(0xffffffffu, dv, 2 * p + 1);
            float2 h0 = upk(acc[p][0]), h1 = upk(acc[p][1]);
            float2 h2 = upk(acc[p][2]), h3 = upk(acc[p][3]);
            float4 o0, o1;
            o0.x = fmaxf((h0.x - mu0) * r0 * gv.x + bv.x, 0.f) * g0;
            o0.y = fmaxf((h1.x - mu0) * r0 * gv.y + bv.y, 0.f) * g0;
            o0.z = fmaxf((h2.x - mu0) * r0 * gv.z + bv.z, 0.f) * g0;
            o0.w = fmaxf((h3.x - mu0) * r0 * gv.w + bv.w, 0.f) * g0;
            o1.x = fmaxf((h0.y - mu1) * r1 * gv.x + bv.x, 0.f) * g1;
            o1.y = fmaxf((h1.y - mu1) * r1 * gv.y + bv.y, 0.f) * g1;
            o1.z = fmaxf((h2.y - mu1) * r1 * gv.z + bv.z, 0.f) * g1;
            o1.w = fmaxf((h3.y - mu1) * r1 * gv.w + bv.w, 0.f) * g1;
            red4(&g_P[d0 * ND + 4 * l], o0);
            red4(&g_P[d1 * ND + 4 * l], o1);
        }
        if (l < 16) atomicAdd(&g_G[dv], sg[w][l]);
    }
}

// GRU, 16 nodes/block (8 pairs). Phase1: gi -> smem; Phase2: gh in same regs.
__global__ void __launch_bounds__(128) k_gru(const float* __restrict__ nf,
                                             const float* __restrict__ bih,
                                             const float* __restrict__ bhh,
                                             float* __restrict__ out) {
    __shared__ __align__(16) float sap[8][ND * 2], snp[8][ND * 2];
    __shared__ u64 sgi[8][3][ND];
    int j = threadIdx.x;
    int base = blockIdx.x * 16;
    #pragma unroll
    for (int n = 0; n < 16; n++) {
        sap[n >> 1][j * 2 + (n & 1)] = g_P[(base + n) * ND + j];
        snp[n >> 1][j * 2 + (n & 1)] = nf[(base + n) * ND + j];
    }
    __syncthreads();
    u64 a0[8], a1[8], a2[8];
    {
        u64 b0 = pk(bih[j], bih[j]), b1_ = pk(bih[ND + j], bih[ND + j]),
            b2_ = pk(bih[2 * ND + j], bih[2 * ND + j]);
        float bf0 = g_bf[j], bf1 = g_bf[ND + j], bf2 = g_bf[2 * ND + j];
        #pragma unroll
        for (int p = 0; p < 8; p++) {
            u64 gp = pk(g_G[base + 2 * p], g_G[base + 2 * p + 1]);
            a0[p] = fma2(gp, pk(bf0, bf0), b0);
            a1[p] = fma2(gp, pk(bf1, bf1), b1_);
            a2[p] = fma2(gp, pk(bf2, bf2), b2_);
        }
    }
    #pragma unroll 2
    for (int k = 0; k < ND; k += 2) {
        float w00 = g_Wf[k * 384 + j],          w01 = g_Wf[(k + 1) * 384 + j];
        float w10 = g_Wf[k * 384 + ND + j],     w11 = g_Wf[(k + 1) * 384 + ND + j];
        float w20 = g_Wf[k * 384 + 2 * ND + j], w21 = g_Wf[(k + 1) * 384 + 2 * ND + j];
        u64 p00 = pk(w00, w00), p01 = pk(w01, w01);
        u64 p10 = pk(w10, w10), p11 = pk(w11, w11);
        u64 p20 = pk(w20, w20), p21 = pk(w21, w21);
        #pragma unroll
        for (int p = 0; p < 8; p++) {
            ulonglong2 xx = *(const ulonglong2*)&(((const u64*)sap[p])[k]);
            a0[p] = fma2(xx.x, p00, a0[p]); a0[p] = fma2(xx.y, p01, a0[p]);
            a1[p] = fma2(xx.x, p10, a1[p]); a1[p] = fma2(xx.y, p11, a1[p]);
            a2[p] = fma2(xx.x, p20, a2[p]); a2[p] = fma2(xx.y, p21, a2[p]);
        }
    }
    #pragma unroll
    for (int p = 0; p < 8; p++) {
        sgi[p][0][j] = a0[p]; sgi[p][1][j] = a1[p]; sgi[p][2][j] = a2[p];
    }
    {
        u64 c0 = pk(bhh[j], bhh[j]), c1 = pk(bhh[ND + j], bhh[ND + j]),
            c2 = pk(bhh[2 * ND + j], bhh[2 * ND + j]);
        #pragma unroll
        for (int p = 0; p < 8; p++) { a0[p] = c0; a1[p] = c1; a2[p] = c2; }
    }
    #pragma unroll 2
    for (int k = 0; k < ND; k += 2) {
        float w00 = g_WtH[k * 384 + j],          w01 = g_WtH[(k + 1) * 384 + j];
        float w10 = g_WtH[k * 384 + ND + j],     w11 = g_WtH[(k + 1) * 384 + ND + j];
        float w20 = g_WtH[k * 384 + 2 * ND + j], w21 = g_WtH[(k + 1) * 384 + 2 * ND + j];
        u64 p00 = pk(w00, w00), p01 = pk(w01, w01);
        u64 p10 = pk(w10, w10), p11 = pk(w11, w11);
        u64 p20 = pk(w20, w20), p21 = pk(w21, w21);
        #pragma unroll
        for (int p = 0; p < 8; p++) {
            ulonglong2 xx = *(const ulonglong2*)&(((const u64*)snp[p])[k]);
            a0[p] = fma2(xx.x, p00, a0[p]); a0[p] = fma2(xx.y, p01, a0[p]);
            a1[p] = fma2(xx.x, p10, a1[p]); a1[p] = fma2(xx.y, p11, a1[p]);
            a2[p] = fma2(xx.x, p20, a2[p]); a2[p] = fma2(xx.y, p21, a2[p]);
        }
    }
    #pragma unroll
    for (int p = 0; p < 8; p++) {
        float2 i0 = upk(sgi[p][0][j]), i1 = upk(sgi[p][1][j]), i2 = upk(sgi[p][2][j]);
        float2 h0 = upk(a0[p]), h1 = upk(a1[p]), h2 = upk(a2[p]);
        float r0 = fsig(i0.x + h0.x), r1 = fsig(i0.y + h0.y);
        float z0 = fsig(i1.x + h1.x), z1 = fsig(i1.y + h1.y);
        float n0 = ftanh(i2.x + r0 * h2.x), n1 = ftanh(i2.y + r1 * h2.y);
        out[(base + 2 * p) * ND + j]     = (1.f - z0) * n0 + z0 * snp[p][j * 2];
        out[(base + 2 * p + 1) * ND + j] = (1.f - z1) * n1 + z1 * snp[p][j * 2 + 1];
    }
}

extern "C" void kernel_launch(void* const* d_in, const int* in_sizes, int n_in,
                              void* d_out, int out_size) {
    const float* nf  = (const float*)d_in[0];
    const int*   ei  = (const int*)d_in[1];
    const float* ef  = (const float*)d_in[2];
    const float* W1  = (const float*)d_in[3];
    const float* b1  = (const float*)d_in[4];
    const float* lng = (const float*)d_in[5];
    const float* lnb = (const float*)d_in[6];
    const float* W2  = (const float*)d_in[7];
    const float* b2  = (const float*)d_in[8];
    const float* gw  = (const float*)d_in[9];
    const float* gb  = (const float*)d_in[10];
    const float* Wih = (const float*)d_in[11];
    const float* bih = (const float*)d_in[12];
    const float* Whh = (const float*)d_in[13];
    const float* bhh = (const float*)d_in[14];
    float* out = (float*)d_out;

    k_zero<<<(NN * ND / 4 + 255) / 256, 256>>>();
    k_transH<<<(384 * ND + 255) / 256, 256>>>(Whh);
    k_fold<<<ND, 384>>>(W2, Wih, b2);
    k_nodeAB<<<NN / 16, 128>>>(nf, W1);
    k_edge<<<2368, 128>>>(ef, ei, W1, b1, lng, lnb, gw, gb);
    k_gru<<<NN / 16, 128>>>(nf, bih, bhh, out);
}

// round 7
// speedup vs baseline: 4.3593x; 1.2248x over previous
#include <cuda_runtime.h>
#include <cuda_bf16.h>

#define NN 40000
#define NE 640000
#define ND 128
#define ED 64

typedef unsigned long long u64;

// Scratch (static device allocations — allowed)
__device__ float g_AB[NN * 256];      // per-node A|B = nf@W1a | nf@W1b
__device__ float g_P[NN * ND];        // scatter target: sum of gate*relu(ln(h))
__device__ float g_G[NN];             // scatter target: sum of gates
__device__ float g_WtH[ND * 384];     // W_hh transposed [k][m]
__device__ float g_Wf[ND * 384];      // Wfold[q][m] = sum_k W2[q][k]*W_ih[m][k]
__device__ float g_bf[384];           // bfold[m]    = sum_k b2[k]  *W_ih[m][k]
// Pre-packed bf16-split B fragments for mma.m16n8k16: uint4{bh0,bh1,bl0,bl1}
__device__ uint4 g_Bab[32 * 8 * 32];  // [nt=32][k16=8][lane=32]  (W1 a|b, 256 cols)
__device__ uint4 g_Bgi[48 * 8 * 32];  // Wfold (384 cols)
__device__ uint4 g_Bgh[48 * 8 * 32];  // WtH   (384 cols)

// ---- packed f32x2 helpers ----
__device__ __forceinline__ u64 pk(float a, float b) {
    u64 d; asm("mov.b64 %0, {%1,%2};" : "=l"(d)
               : "r"(__float_as_uint(a)), "r"(__float_as_uint(b)));
    return d;
}
__device__ __forceinline__ float2 upk(u64 v) {
    unsigned a, b; asm("mov.b64 {%0,%1}, %2;" : "=r"(a), "=r"(b) : "l"(v));
    return make_float2(__uint_as_float(a), __uint_as_float(b));
}
__device__ __forceinline__ u64 fma2(u64 a, u64 b, u64 c) {
    u64 d; asm("fma.rn.f32x2 %0, %1, %2, %3;" : "=l"(d) : "l"(a), "l"(b), "l"(c));
    return d;
}
__device__ __forceinline__ u64 add2(u64 a, u64 b) {
    u64 d; asm("add.rn.f32x2 %0, %1, %2;" : "=l"(d) : "l"(a), "l"(b));
    return d;
}
__device__ __forceinline__ u64 mul2(u64 a, u64 b) {
    u64 d; asm("mul.rn.f32x2 %0, %1, %2;" : "=l"(d) : "l"(a), "l"(b));
    return d;
}
__device__ __forceinline__ void red4(float* p, float4 v) {
    asm volatile("red.global.add.v4.f32 [%0], {%1, %2, %3, %4};"
                 :: "l"(p), "f"(v.x), "f"(v.y), "f"(v.z), "f"(v.w) : "memory");
}
__device__ __forceinline__ float fsig(float x) { return 1.f / (1.f + __expf(-x)); }
__device__ __forceinline__ float ftanh(float x) {
    float e = __expf(2.f * fabsf(x));
    return copysignf(1.f - 2.f / (e + 1.f), x);
}

// ---- bf16-split helpers ----
__device__ __forceinline__ unsigned bfpack(float x0, float x1) {
    // reg = {lo16: x0, hi16: x1}
    unsigned r; asm("cvt.rn.bf16x2.f32 %0, %1, %2;" : "=r"(r) : "f"(x1), "f"(x0));
    return r;
}
__device__ __forceinline__ void bfsplit(float x0, float x1, unsigned& h, unsigned& lo) {
    h = bfpack(x0, x1);
    __nv_bfloat162 hb = *(__nv_bfloat162*)&h;
    float l0 = x0 - __bfloat162float(hb.x);
    float l1 = x1 - __bfloat162float(hb.y);
    lo = bfpack(l0, l1);
}
__device__ __forceinline__ void mma16(float* c, const unsigned* a, unsigned b0, unsigned b1) {
    asm("mma.sync.aligned.m16n8k16.row.col.f32.bf16.bf16.f32 "
        "{%0,%1,%2,%3},{%4,%5,%6,%7},{%8,%9},{%0,%1,%2,%3};"
        : "+f"(c[0]), "+f"(c[1]), "+f"(c[2]), "+f"(c[3])
        : "r"(a[0]), "r"(a[1]), "r"(a[2]), "r"(a[3]), "r"(b0), "r"(b1));
}

__global__ void k_zero() {
    int i = blockIdx.x * blockDim.x + threadIdx.x;
    if (i < NN * ND / 4)
        reinterpret_cast<float4*>(g_P)[i] = make_float4(0.f, 0.f, 0.f, 0.f);
    if (i < NN / 4)
        reinterpret_cast<float4*>(g_G)[i] = make_float4(0.f, 0.f, 0.f, 0.f);
}

__global__ void k_transH(const float* __restrict__ Whh) {
    int idx = blockIdx.x * blockDim.x + threadIdx.x;
    if (idx < 384 * ND) {
        int k = idx / 384, m = idx % 384;
        g_WtH[idx] = Whh[m * ND + k];
    }
}

// Fold W2 into GRU input weights
__global__ void __launch_bounds__(384) k_fold(const float* __restrict__ W2,
                                              const float* __restrict__ Wih,
                                              const float* __restrict__ b2) {
    __shared__ float sw[ND], sb[ND];
    int q = blockIdx.x, m = threadIdx.x;
    if (m < ND) { sw[m] = W2[q * ND + m]; sb[m] = b2[m]; }
    __syncthreads();
    float acc = 0.f, accb = 0.f;
    const float* wr = Wih + m * ND;
    #pragma unroll 4
    for (int k = 0; k < ND; k++) {
        float w = wr[k];
        acc  = fmaf(sw[k], w, acc);
        accb = fmaf(sb[k], w, accb);
    }
    g_Wf[q * 384 + m] = acc;
    if (q == 0) g_bf[m] = accb;
}

// Pack B fragments (bf16 hi/lo) for the three GEMM weight matrices.
// Fragment (m16n8k16, B col-major): b0 = {B[kb][n], B[kb+1][n]}, b1 = {B[kb+8][n], B[kb+9][n]},
// kb = k16*16 + 2*(lane&3), n = nt*8 + (lane>>2).
__global__ void k_prep(const float* __restrict__ W1) {
    int i = blockIdx.x * 256 + threadIdx.x;   // 0..32767
    int lane = i & 31;
    int n8 = lane >> 2, kq = lane & 3;
    unsigned h0, l0, h1, l1;
    if (i < 8192) {                            // g_Bab from W1 (rows 0..255)
        int k16 = (i >> 5) & 7, nt = i >> 8;
        int nn = nt * 8 + n8, kb = k16 * 16 + 2 * kq;
        const float* base = (nn < 128) ? (W1 + nn) : (W1 + 128 * 128 + nn - 128);
        bfsplit(base[kb * 128], base[(kb + 1) * 128], h0, l0);
        bfsplit(base[(kb + 8) * 128], base[(kb + 9) * 128], h1, l1);
        g_Bab[i] = make_uint4(h0, h1, l0, l1);
    } else if (i < 8192 + 12288) {             // g_Bgi from g_Wf [k][384]
        int ii = i - 8192;
        int k16 = (ii >> 5) & 7, nt = ii >> 8;
        int nn = nt * 8 + n8, kb = k16 * 16 + 2 * kq;
        bfsplit(g_Wf[kb * 384 + nn], g_Wf[(kb + 1) * 384 + nn], h0, l0);
        bfsplit(g_Wf[(kb + 8) * 384 + nn], g_Wf[(kb + 9) * 384 + nn], h1, l1);
        g_Bgi[ii] = make_uint4(h0, h1, l0, l1);
    } else {                                   // g_Bgh from g_WtH [k][384]
        int ii = i - 8192 - 12288;
        int k16 = (ii >> 5) & 7, nt = ii >> 8;
        int nn = nt * 8 + n8, kb = k16 * 16 + 2 * kq;
        bfsplit(g_WtH[kb * 384 + nn], g_WtH[(kb + 1) * 384 + nn], h0, l0);
        bfsplit(g_WtH[(kb + 8) * 384 + nn], g_WtH[(kb + 9) * 384 + nn], h1, l1);
        g_Bgh[ii] = make_uint4(h0, h1, l0, l1);
    }
}

// nodeAB on tensor cores: 32 nodes/block, warp owns 64 cols of 256.
__global__ void __launch_bounds__(128) k_nodeAB_t(const float* __restrict__ nf) {
    __shared__ unsigned sah[32][68], sal[32][68];   // bf16x2 k-pairs (64 used)
    int t = threadIdx.x, l = t & 31, w = t >> 5;
    int base = blockIdx.x * 32;
    for (int i = t; i < 32 * 64; i += 128) {
        int r = i >> 6, pc = i & 63;
        float2 v = *(const float2*)&nf[(base + r) * ND + pc * 2];
        unsigned h, lo; bfsplit(v.x, v.y, h, lo);
        sah[r][pc] = h; sal[r][pc] = lo;
    }
    __syncthreads();
    float acc[2][8][4];
    #pragma unroll
    for (int m = 0; m < 2; m++)
        #pragma unroll
        for (int n = 0; n < 8; n++)
            #pragma unroll
            for (int x = 0; x < 4; x++) acc[m][n][x] = 0.f;
    int r0 = l >> 2, c0 = l & 3;
    #pragma unroll
    for (int k16 = 0; k16 < 8; k16++) {
        unsigned ah[2][4], al[2][4];
        int kp = k16 * 8 + c0;
        #pragma unroll
        for (int m = 0; m < 2; m++) {
            ah[m][0] = sah[m * 16 + r0][kp];     ah[m][1] = sah[m * 16 + r0 + 8][kp];
            ah[m][2] = sah[m * 16 + r0][kp + 4]; ah[m][3] = sah[m * 16 + r0 + 8][kp + 4];
            al[m][0] = sal[m * 16 + r0][kp];     al[m][1] = sal[m * 16 + r0 + 8][kp];
            al[m][2] = sal[m * 16 + r0][kp + 4]; al[m][3] = sal[m * 16 + r0 + 8][kp + 4];
        }
        #pragma unroll
        for (int n = 0; n < 8; n++) {
            uint4 bv = g_Bab[((w * 8 + n) * 8 + k16) * 32 + l];
            #pragma unroll
            for (int m = 0; m < 2; m++) {
                mma16(acc[m][n], ah[m], bv.x, bv.y);
                mma16(acc[m][n], al[m], bv.x, bv.y);
                mma16(acc[m][n], ah[m], bv.z, bv.w);
            }
        }
    }
    #pragma unroll
    for (int m = 0; m < 2; m++)
        #pragma unroll
        for (int n = 0; n < 8; n++) {
            int row = base + m * 16 + r0;
            int col = w * 64 + n * 8 + 2 * c0;
            *(float2*)&g_AB[row * 256 + col]       = make_float2(acc[m][n][0], acc[m][n][1]);
            *(float2*)&g_AB[(row + 8) * 256 + col] = make_float2(acc[m][n][2], acc[m][n][3]);
        }
}

// Edge kernel: warp-autonomous (unchanged from R6).
__global__ void __launch_bounds__(128, 4) k_edge(
    const float* __restrict__ ef, const int* __restrict__ ei,
    const float* __restrict__ W1, const float* __restrict__ b1,
    const float* __restrict__ lng, const float* __restrict__ lnb,
    const float* __restrict__ gw, const float* __restrict__ gb) {
    __shared__ __align__(16) float sef[4][8 * 132];
    __shared__ float sg[4][16];
    int t = threadIdx.x, l = t & 31, w = t >> 5;
    float* mysef = sef[w];
    float4 b1v = *(const float4*)&b1[4 * l];
    float4 gv  = *(const float4*)&lng[4 * l];
    float4 bv  = *(const float4*)&lnb[4 * l];
    float gb0 = gb[0];
    const float4* WC = (const float4*)(W1 + 256 * ND) + l;

    for (int e0 = (blockIdx.x * 4 + w) * 16; e0 < NE; e0 += gridDim.x * 64) {
        __syncwarp();
        int sv = ei[e0 + (l & 15)];
        int dv = ei[NE + e0 + (l & 15)];
        #pragma unroll
        for (int q = 0; q < 8; q++) {
            float2 v0 = *(const float2*)&ef[(e0 + 2 * q) * ED + 2 * l];
            float2 v1 = *(const float2*)&ef[(e0 + 2 * q + 1) * ED + 2 * l];
            *(float4*)&mysef[q * 132 + 4 * l] = make_float4(v0.x, v1.x, v0.y, v1.y);
        }
        __syncwarp();

        {
            int e = l >> 1, p = e >> 1, h = e & 1, k0 = (l & 1) * 32;
            const float* base = &mysef[p * 132 + h];
            float gd = 0.f;
            #pragma unroll
            for (int i = 0; i < 32; i++)
                gd = fmaf(base[(k0 + i) * 2], gw[k0 + i], gd);
            gd += __shfl_xor_sync(0xffffffffu, gd, 1);
            if ((l & 1) == 0) sg[w][e] = fsig(gd + gb0);
        }

        u64 acc[8][4];
        #pragma unroll
        for (int p = 0; p < 8; p++) {
            int s0 = __shfl_sync(0xffffffffu, sv, 2 * p);
            int s1 = __shfl_sync(0xffffffffu, sv, 2 * p + 1);
            int d0 = __shfl_sync(0xffffffffu, dv, 2 * p);
            int d1 = __shfl_sync(0xffffffffu, dv, 2 * p + 1);
            float4 A0 = *(const float4*)&g_AB[s0 * 256 + 4 * l];
            float4 A1 = *(const float4*)&g_AB[s1 * 256 + 4 * l];
            float4 B0 = *(const float4*)&g_AB[d0 * 256 + ND + 4 * l];
            float4 B1 = *(const float4*)&g_AB[d1 * 256 + ND + 4 * l];
            acc[p][0] = pk(b1v.x + A0.x + B0.x, b1v.x + A1.x + B1.x);
            acc[p][1] = pk(b1v.y + A0.y + B0.y, b1v.y + A1.y + B1.y);
            acc[p][2] = pk(b1v.z + A0.z + B0.z, b1v.z + A1.z + B1.z);
            acc[p][3] = pk(b1v.w + A0.w + B0.w, b1v.w + A1.w + B1.w);
        }

        #pragma unroll 1
        for (int k = 0; k < ED; k += 2) {
            float4 w0 = WC[k * 32];
            float4 w1 = WC[(k + 1) * 32];
            u64 w0x = pk(w0.x, w0.x), w0y = pk(w0.y, w0.y);
            u64 w0z = pk(w0.z, w0.z), w0w = pk(w0.w, w0.w);
            u64 w1x = pk(w1.x, w1.x), w1y = pk(w1.y, w1.y);
            u64 w1z = pk(w1.z, w1.z), w1w = pk(w1.w, w1.w);
            #pragma unroll
            for (int p = 0; p < 8; p++) {
                ulonglong2 xx = *(const ulonglong2*)&mysef[p * 132 + 2 * k];
                acc[p][0] = fma2(xx.x, w0x, acc[p][0]);
                acc[p][1] = fma2(xx.x, w0y, acc[p][1]);
                acc[p][2] = fma2(xx.x, w0z, acc[p][2]);
                acc[p][3] = fma2(xx.x, w0w, acc[p][3]);
                acc[p][0] = fma2(xx.y, w1x, acc[p][0]);
                acc[p][1] = fma2(xx.y, w1y, acc[p][1]);
                acc[p][2] = fma2(xx.y, w1z, acc[p][2]);
                acc[p][3] = fma2(xx.y, w1w, acc[p][3]);
            }
        }

        u64 sum[8], sq[8];
        #pragma unroll
        for (int p = 0; p < 8; p++) {
            sum[p] = add2(add2(acc[p][0], acc[p][1]), add2(acc[p][2], acc[p][3]));
            sq[p]  = add2(add2(mul2(acc[p][0], acc[p][0]), mul2(acc[p][1], acc[p][1])),
                          add2(mul2(acc[p][2], acc[p][2]), mul2(acc[p][3], acc[p][3])));
        }
        #pragma unroll
        for (int o = 16; o; o >>= 1) {
            #pragma unroll
            for (int p = 0; p < 8; p++) {
                sum[p] = add2(sum[p], __shfl_xor_sync(0xffffffffu, sum[p], o));
                sq[p]  = add2(sq[p],  __shfl_xor_sync(0xffffffffu, sq[p],  o));
            }
        }
        __syncwarp();

        #pragma unroll
        for (int p = 0; p < 8; p++) {
            float2 s = upk(sum[p]), s2 = upk(sq[p]);
            float mu0 = s.x * (1.f / ND), mu1 = s.y * (1.f / ND);
            float r0 = rsqrtf(s2.x * (1.f / ND) - mu0 * mu0 + 1e-5f);
            float r1 = rsqrtf(s2.y * (1.f / ND) - mu1 * mu1 + 1e-5f);
            float g0 = sg[w][2 * p], g1 = sg[w][2 * p + 1];
            int d0 = __shfl_sync(0xffffffffu, dv, 2 * p);
            int d1 = __shfl_sync(0xffffffffu, dv, 2 * p + 1);
            float2 h0 = upk(acc[p][0]), h1 = upk(acc[p][1]);
            float2 h2 = upk(acc[p][2]), h3 = upk(acc[p][3]);
            float4 o0, o1;
            o0.x = fmaxf((h0.x - mu0) * r0 * gv.x + bv.x, 0.f) * g0;
            o0.y = fmaxf((h1.x - mu0) * r0 * gv.y + bv.y, 0.f) * g0;
            o0.z = fmaxf((h2.x - mu0) * r0 * gv.z + bv.z, 0.f) * g0;
            o0.w = fmaxf((h3.x - mu0) * r0 * gv.w + bv.w, 0.f) * g0;
            o1.x = fmaxf((h0.y - mu1) * r1 * gv.x + bv.x, 0.f) * g1;
            o1.y = fmaxf((h1.y - mu1) * r1 * gv.y + bv.y, 0.f) * g1;
            o1.z = fmaxf((h2.y - mu1) * r1 * gv.z + bv.z, 0.f) * g1;
            o1.w = fmaxf((h3.y - mu1) * r1 * gv.w + bv.w, 0.f) * g1;
            red4(&g_P[d0 * ND + 4 * l], o0);
            red4(&g_P[d1 * ND + 4 * l], o1);
        }
        if (l < 16) atomicAdd(&g_G[dv], sg[w][l]);
    }
}

// GRU on tensor cores: 16 nodes/block; warp owns cols [w*32, w*32+32) of each gate.
// Phase1 gi -> smem (stride 49), phase2 gh reuses accumulators; combine locally.
__global__ void __launch_bounds__(128) k_gru_t(const float* __restrict__ nf,
                                               const float* __restrict__ bih,
                                               const float* __restrict__ bhh,
                                               float* __restrict__ out) {
    __shared__ unsigned sph[16][68], spl[16][68], snh[16][68], snl[16][68];
    __shared__ float snraw[16][132];
    __shared__ float sgi[128][49];
    int t = threadIdx.x, l = t & 31, w = t >> 5;
    int base = blockIdx.x * 16;
    for (int i = t; i < 16 * 64; i += 128) {
        int r = i >> 6, pc = i & 63;
        float2 vp = *(const float2*)&g_P[(base + r) * ND + pc * 2];
        float2 vn = *(const float2*)&nf[(base + r) * ND + pc * 2];
        unsigned h, lo;
        bfsplit(vp.x, vp.y, h, lo); sph[r][pc] = h; spl[r][pc] = lo;
        bfsplit(vn.x, vn.y, h, lo); snh[r][pc] = h; snl[r][pc] = lo;
        snraw[r][pc * 2] = vn.x; snraw[r][pc * 2 + 1] = vn.y;
    }
    __syncthreads();
    int r0 = l >> 2, c0 = l & 3;
    float acc[12][4];

    // phase 1: gi = P @ Wfold
    #pragma unroll
    for (int j = 0; j < 12; j++)
        #pragma unroll
        for (int x = 0; x < 4; x++) acc[j][x] = 0.f;
    #pragma unroll
    for (int k16 = 0; k16 < 8; k16++) {
        unsigned ah[4], al[4];
        int kp = k16 * 8 + c0;
        ah[0] = sph[r0][kp];     ah[1] = sph[r0 + 8][kp];
        ah[2] = sph[r0][kp + 4]; ah[3] = sph[r0 + 8][kp + 4];
        al[0] = spl[r0][kp];     al[1] = spl[r0 + 8][kp];
        al[2] = spl[r0][kp + 4]; al[3] = spl[r0 + 8][kp + 4];
        #pragma unroll
        for (int j = 0; j < 12; j++) {
            int nt = (j >> 2) * 16 + w * 4 + (j & 3);
            uint4 bvv = g_Bgi[(nt * 8 + k16) * 32 + l];
            mma16(acc[j], ah, bvv.x, bvv.y);
            mma16(acc[j], al, bvv.x, bvv.y);
            mma16(acc[j], ah, bvv.z, bvv.w);
        }
    }
    #pragma unroll
    for (int j = 0; j < 12; j++)
        #pragma unroll
        for (int x = 0; x < 4; x++) sgi[t][j * 4 + x] = acc[j][x];

    // phase 2: gh = nf @ WtH
    #pragma unroll
    for (int j = 0; j < 12; j++)
        #pragma unroll
        for (int x = 0; x < 4; x++) acc[j][x] = 0.f;
    #pragma unroll
    for (int k16 = 0; k16 < 8; k16++) {
        unsigned ah[4], al[4];
        int kp = k16 * 8 + c0;
        ah[0] = snh[r0][kp];     ah[1] = snh[r0 + 8][kp];
        ah[2] = snh[r0][kp + 4]; ah[3] = snh[r0 + 8][kp + 4];
        al[0] = snl[r0][kp];     al[1] = snl[r0 + 8][kp];
        al[2] = snl[r0][kp + 4]; al[3] = snl[r0 + 8][kp + 4];
        #pragma unroll
        for (int j = 0; j < 12; j++) {
            int nt = (j >> 2) * 16 + w * 4 + (j & 3);
            uint4 bvv = g_Bgh[(nt * 8 + k16) * 32 + l];
            mma16(acc[j], ah, bvv.x, bvv.y);
            mma16(acc[j], al, bvv.x, bvv.y);
            mma16(acc[j], ah, bvv.z, bvv.w);
        }
    }

    // combine
    float G0 = g_G[base + r0], G1 = g_G[base + r0 + 8];
    #pragma unroll
    for (int j = 0; j < 4; j++) {
        int colg = w * 32 + j * 8 + 2 * c0;
        float2 o0, o1;
        #pragma unroll
        for (int b = 0; b < 2; b++) {
            int col = colg + b;
            float bfr = g_bf[col], bfz = g_bf[128 + col], bfn = g_bf[256 + col];
            float bir = bih[col], biz = bih[128 + col], bin = bih[256 + col];
            float bhr = bhh[col], bhz = bhh[128 + col], bhn = bhh[256 + col];
            {   // row r0
                float gir = sgi[t][j * 4 + b]       + bir + G0 * bfr;
                float giz = sgi[t][(j + 4) * 4 + b] + biz + G0 * bfz;
                float gin = sgi[t][(j + 8) * 4 + b] + bin + G0 * bfn;
                float ghr = acc[j][b] + bhr, ghz = acc[j + 4][b] + bhz, ghn = acc[j + 8][b] + bhn;
                float rr = fsig(gir + ghr), zz = fsig(giz + ghz);
                float nv = ftanh(gin + rr * ghn);
                float xo = (1.f - zz) * nv + zz * snraw[r0][col];
                if (b) o0.y = xo; else o0.x = xo;
            }
            {   // row r0+8
                float gir = sgi[t][j * 4 + b + 2]       + bir + G1 * bfr;
                float giz = sgi[t][(j + 4) * 4 + b + 2] + biz + G1 * bfz;
                float gin = sgi[t][(j + 8) * 4 + b + 2] + bin + G1 * bfn;
                float ghr = acc[j][b + 2] + bhr, ghz = acc[j + 4][b + 2] + bhz, ghn = acc[j + 8][b + 2] + bhn;
                float rr = fsig(gir + ghr), zz = fsig(giz + ghz);
                float nv = ftanh(gin + rr * ghn);
                float xo = (1.f - zz) * nv + zz * snraw[r0 + 8][col];
                if (b) o1.y = xo; else o1.x = xo;
            }
        }
        *(float2*)&out[(base + r0) * ND + colg]     = o0;
        *(float2*)&out[(base + r0 + 8) * ND + colg] = o1;
    }
}

extern "C" void kernel_launch(void* const* d_in, const int* in_sizes, int n_in,
                              void* d_out, int out_size) {
    const float* nf  = (const float*)d_in[0];
    const int*   ei  = (const int*)d_in[1];
    const float* ef  = (const float*)d_in[2];
    const float* W1  = (const float*)d_in[3];
    const float* b1  = (const float*)d_in[4];
    const float* lng = (const float*)d_in[5];
    const float* lnb = (const float*)d_in[6];
    const float* W2  = (const float*)d_in[7];
    const float* b2  = (const float*)d_in[8];
    const float* gw  = (const float*)d_in[9];
    const float* gb  = (const float*)d_in[10];
    const float* Wih = (const float*)d_in[11];
    const float* bih = (const float*)d_in[12];
    const float* Whh = (const float*)d_in[13];
    const float* bhh = (const float*)d_in[14];
    float* out = (float*)d_out;

    k_zero<<<(NN * ND / 4 + 255) / 256, 256>>>();
    k_transH<<<(384 * ND + 255) / 256, 256>>>(Whh);
    k_fold<<<ND, 384>>>(W2, Wih, b2);
    k_prep<<<128, 256>>>(W1);
    k_nodeAB_t<<<NN / 32, 128>>>(nf);
    k_edge<<<2368, 128>>>(ef, ei, W1, b1, lng, lnb, gw, gb);
    k_gru_t<<<NN / 16, 128>>>(nf, bih, bhh, out);
}